// round 11
// baseline (speedup 1.0000x reference)
#include <cuda_runtime.h>
#include <cuda_fp16.h>
#include <cstdint>
#include <cstddef>

// ---------------------------------------------------------------------------
// GTrXLCell round 11: warp tile 64x64 (2x2 warps, 128 threads/CTA), occ=2.
// Crossbar model (validated rounds 8-10): smem bytes/ktile drop 128KB->96KB
// => tensor ceiling 50% -> 67%. 256 regs/thread available at 128thr+occ2.
// Wvo fusion (round 10) kept: ctx = qn @ Wvo^T + bvo, Wvo = Wo@Wv.
// ---------------------------------------------------------------------------

#define B_DIM     4096
#define D_MODEL   2048
#define D_FF      8192

__device__ float  g_hhat[(size_t)B_DIM * D_MODEL];
__device__ __half g_x16 [(size_t)B_DIM * 1024];
__device__ __half g_xh  [(size_t)B_DIM * D_MODEL];
__device__ __half g_qn16[(size_t)B_DIM * D_MODEL];
__device__ __half g_y16 [(size_t)B_DIM * D_MODEL];
__device__ __half g_t16 [(size_t)B_DIM * D_FF];
__device__ __half g_wp16 [(size_t)D_MODEL * 1024];
__device__ __half g_wvT16[(size_t)D_MODEL * D_MODEL];
__device__ __half g_wo16 [(size_t)D_MODEL * D_MODEL];
__device__ __half g_wvo16[(size_t)D_MODEL * D_MODEL];
__device__ float  g_bvo  [D_MODEL];
__device__ float  g_zb   [D_MODEL];
__device__ __half g_w1_16[(size_t)D_FF * D_MODEL];
__device__ __half g_w2_16[(size_t)D_MODEL * D_FF];

// ------------------------------ helpers -----------------------------------
__device__ __forceinline__ uint32_t smem_u32(const void* p) {
    uint32_t a;
    asm("{ .reg .u64 t; cvta.to.shared.u64 t, %1; cvt.u32.u64 %0, t; }"
        : "=r"(a) : "l"(p));
    return a;
}
__device__ __forceinline__ void cp16(uint32_t dst, const void* src) {
    asm volatile("cp.async.cg.shared.global [%0], [%1], 16;"
                 :: "r"(dst), "l"(src));
}
#define CP_COMMIT() asm volatile("cp.async.commit_group;" ::: "memory")
#define CP_WAIT1()  asm volatile("cp.async.wait_group 1;" ::: "memory")
#define CP_WAIT0()  asm volatile("cp.async.wait_group 0;" ::: "memory")

__device__ __forceinline__ void ldsm_x4(uint32_t& r0, uint32_t& r1,
                                        uint32_t& r2, uint32_t& r3, uint32_t addr) {
    asm volatile("ldmatrix.sync.aligned.m8n8.x4.shared.b16 {%0,%1,%2,%3}, [%4];"
                 : "=r"(r0), "=r"(r1), "=r"(r2), "=r"(r3) : "r"(addr));
}
__device__ __forceinline__ void mma_f16(float c[4], const uint32_t a[4],
                                        const uint32_t b[2]) {
    asm volatile(
        "mma.sync.aligned.m16n8k16.row.col.f32.f16.f16.f32 "
        "{%0,%1,%2,%3}, {%4,%5,%6,%7}, {%8,%9}, {%0,%1,%2,%3};\n"
        : "+f"(c[0]), "+f"(c[1]), "+f"(c[2]), "+f"(c[3])
        : "r"(a[0]), "r"(a[1]), "r"(a[2]), "r"(a[3]), "r"(b[0]), "r"(b[1]));
}
__device__ __forceinline__ float sigmoidf_(float x) { return 1.0f / (1.0f + expf(-x)); }
__device__ __forceinline__ float gelu_exact(float x) {
    return 0.5f * x * (1.0f + erff(x * 0.70710678118654752f));
}

// ---------------------------------------------------------------------------
// fp16 GEMM: C = A @ Bw^T + bias (+epilogue).
// BM=BN=128, BK=64 halves, 3-stage cp.async ring, 1 barrier/ktile.
// 128 threads = 4 warps (2x2), warp tile 64x64, occ=2.
// ---------------------------------------------------------------------------
constexpr int BM = 128, BN = 128, BKH = 64;
constexpr int LDT = 72;
constexpr int TILE_A = BM * LDT;                               // 9216 halves
constexpr uint32_t STAGE_BYTES = 2u * (uint32_t)TILE_A * 2u;   // 36864 B
constexpr int STAGES = 3;
constexpr uint32_t GSMEM = STAGES * STAGE_BYTES;               // 110592 B
constexpr int NTHR = 128;

template <int MODE, int OUT32, int OUT16>
__global__ void __launch_bounds__(NTHR, 2) gemm16(
    const __half* __restrict__ A, const __half* __restrict__ Bw,
    const float* __restrict__ bias,
    float* __restrict__ C32, __half* __restrict__ C16, float* __restrict__ C32b,
    const float* __restrict__ aux,
    const float* __restrict__ ga, const float* __restrict__ gb,
    int N, int K)
{
    extern __shared__ char smraw[];
    const uint32_t sbase = smem_u32(smraw);

    const int tid  = threadIdx.x;
    const int warp = tid >> 5;          // 0..3
    const int lane = tid & 31;
    const int wm = warp >> 1;           // 0..1  (64 rows)
    const int wn = warp & 1;            // 0..1  (64 cols)
    const int gr = lane >> 2;           // 0..7
    const int tg = lane & 3;            // 0..3

    const int block_row = blockIdx.y * BM;
    const int block_col = blockIdx.x * BN;
    const int KT = K / BKH;

    // staging: 128 threads, each copies 8 A-chunks + 8 B-chunks (16B each),
    // rows r0 + 16*k, fixed column scol. Precomputed arrays (round-7 lesson).
    const int r0   = tid >> 3;                // 0..15
    const int scol = (tid & 7) * 8;           // halves
    const __half* Agp[8];
    const __half* Bgp[8];
    uint32_t dA[8], dB[8];
    #pragma unroll
    for (int k = 0; k < 8; k++) {
        const int rw = r0 + 16 * k;
        Agp[k] = A  + (size_t)(block_row + rw) * K + scol;
        Bgp[k] = Bw + (size_t)(block_col + rw) * K + scol;
        dA[k] = (uint32_t)(rw * LDT + scol) * 2u;
        dB[k] = (uint32_t)(TILE_A + rw * LDT + scol) * 2u;
    }

    // ldmatrix per-lane base offsets (bytes)
    const int j = lane >> 3, r = lane & 7;
    uint32_t aoff[4], boff[4];
    #pragma unroll
    for (int mi = 0; mi < 4; mi++)
        aoff[mi] = (uint32_t)(((wm * 64 + mi * 16 + (j & 1) * 8 + r) * LDT
                               + (j >> 1) * 8) * 2);
    #pragma unroll
    for (int n4 = 0; n4 < 4; n4++)
        boff[n4] = (uint32_t)((TILE_A
                               + (wn * 64 + n4 * 16 + (j >> 1) * 8 + r) * LDT
                               + (j & 1) * 8) * 2);

    float acc[4][8][4];
    #pragma unroll
    for (int mi = 0; mi < 4; mi++)
        #pragma unroll
        for (int ni = 0; ni < 8; ni++)
            #pragma unroll
            for (int q = 0; q < 4; q++) acc[mi][ni][q] = 0.0f;

    auto stage_fill = [&](int kt, int st) {
        const uint32_t sb = sbase + (uint32_t)st * STAGE_BYTES;
        const size_t ko = (size_t)kt * BKH;
        #pragma unroll
        for (int k = 0; k < 8; k++) cp16(sb + dA[k], Agp[k] + ko);
        #pragma unroll
        for (int k = 0; k < 8; k++) cp16(sb + dB[k], Bgp[k] + ko);
        CP_COMMIT();
    };

    stage_fill(0, 0);
    if (KT > 1) stage_fill(1, 1);

    for (int kt = 0; kt < KT; kt++) {
        if (kt + 1 < KT) CP_WAIT1(); else CP_WAIT0();
        __syncthreads();
        if (kt + 2 < KT) {
            int st = (kt + 2) % STAGES;
            stage_fill(kt + 2, st);
        }

        const uint32_t sb = sbase + (uint32_t)(kt % STAGES) * STAGE_BYTES;
        #pragma unroll
        for (int ks = 0; ks < 4; ks++) {
            const uint32_t kk = ks * 32;       // bytes along K (16 halves)
            uint32_t af[4][4];
            #pragma unroll
            for (int mi = 0; mi < 4; mi++)
                ldsm_x4(af[mi][0], af[mi][1], af[mi][2], af[mi][3],
                        sb + aoff[mi] + kk);
            uint32_t bf[8][2];
            #pragma unroll
            for (int n4 = 0; n4 < 4; n4++) {
                uint32_t b0, b1, b2, b3;
                ldsm_x4(b0, b1, b2, b3, sb + boff[n4] + kk);
                bf[n4 * 2][0] = b0; bf[n4 * 2][1] = b1;
                bf[n4 * 2 + 1][0] = b2; bf[n4 * 2 + 1][1] = b3;
            }
            #pragma unroll
            for (int mi = 0; mi < 4; mi++)
                #pragma unroll
                for (int ni = 0; ni < 8; ni++)
                    mma_f16(acc[mi][ni], af[mi], bf[ni]);
        }
    }

    // ----------------------------- epilogue --------------------------------
    #pragma unroll
    for (int mi = 0; mi < 4; mi++) {
        #pragma unroll
        for (int ni = 0; ni < 8; ni++) {
            const int col = block_col + wn * 64 + ni * 8 + 2 * tg;
            const float b0 = bias[col], b1 = bias[col + 1];
            float sa0 = 0.f, sa1 = 0.f, sb0 = 0.f, sb1 = 0.f;
            if (MODE == 1) {
                sa0 = sigmoidf_(ga[col]);     sa1 = sigmoidf_(ga[col + 1]);
                sb0 = sigmoidf_(gb[col]);     sb1 = sigmoidf_(gb[col + 1]);
            }
            #pragma unroll
            for (int h = 0; h < 2; h++) {
                const int row = block_row + wm * 64 + mi * 16 + gr + h * 8;
                float v0 = acc[mi][ni][2 * h + 0] + b0;
                float v1 = acc[mi][ni][2 * h + 1] + b1;
                const size_t off = (size_t)row * N + col;
                if (MODE == 1) {
                    v0 = sa0 * aux[off]     + sb0 * v0;
                    v1 = sa1 * aux[off + 1] + sb1 * v1;
                } else if (MODE == 2) {
                    v0 = gelu_exact(v0);
                    v1 = gelu_exact(v1);
                } else if (MODE == 3) {
                    v0 += aux[off];
                    v1 += aux[off + 1];
                }
                if (OUT32) {
                    float2 o = make_float2(v0, v1);
                    *reinterpret_cast<float2*>(&C32[off]) = o;
                    if (MODE == 3) *reinterpret_cast<float2*>(&C32b[off]) = o;
                }
                if (OUT16)
                    *reinterpret_cast<__half2*>(&C16[off]) = __floats2half2_rn(v0, v1);
            }
        }
    }
}

// ---------------------------------------------------------------------------
// LayerNorm D=2048
// ---------------------------------------------------------------------------
__global__ void __launch_bounds__(256) ln2048_f32in(
    const float* __restrict__ x, const float* __restrict__ g,
    const float* __restrict__ b, __half* __restrict__ out)
{
    constexpr int D = 2048;
    const int row = blockIdx.x;
    const int tid = threadIdx.x;
    const float4* xr = reinterpret_cast<const float4*>(x + (size_t)row * D);

    float4 v0 = xr[tid];
    float4 v1 = xr[tid + 256];
    float s  = v0.x + v0.y + v0.z + v0.w + v1.x + v1.y + v1.z + v1.w;
    float ss = v0.x*v0.x + v0.y*v0.y + v0.z*v0.z + v0.w*v0.w
             + v1.x*v1.x + v1.y*v1.y + v1.z*v1.z + v1.w*v1.w;
    #pragma unroll
    for (int o = 16; o > 0; o >>= 1) {
        s  += __shfl_xor_sync(0xFFFFFFFFu, s,  o);
        ss += __shfl_xor_sync(0xFFFFFFFFu, ss, o);
    }
    __shared__ float sh_s[8], sh_ss[8];
    if ((tid & 31) == 0) { sh_s[tid >> 5] = s; sh_ss[tid >> 5] = ss; }
    __syncthreads();
    float ts = 0.f, tss = 0.f;
    #pragma unroll
    for (int i = 0; i < 8; i++) { ts += sh_s[i]; tss += sh_ss[i]; }
    const float mean = ts * (1.0f / D);
    const float inv  = rsqrtf(tss * (1.0f / D) - mean * mean + 1e-5f);

    const float4* g4 = reinterpret_cast<const float4*>(g);
    const float4* b4 = reinterpret_cast<const float4*>(b);
    __half2* o2 = reinterpret_cast<__half2*>(out + (size_t)row * D);
    float4 ga0 = g4[tid],       gb0 = b4[tid];
    float4 ga1 = g4[tid + 256], gb1 = b4[tid + 256];
    o2[tid * 2]     = __floats2half2_rn((v0.x - mean) * inv * ga0.x + gb0.x,
                                        (v0.y - mean) * inv * ga0.y + gb0.y);
    o2[tid * 2 + 1] = __floats2half2_rn((v0.z - mean) * inv * ga0.z + gb0.z,
                                        (v0.w - mean) * inv * ga0.w + gb0.w);
    o2[(tid + 256) * 2]     = __floats2half2_rn((v1.x - mean) * inv * ga1.x + gb1.x,
                                                (v1.y - mean) * inv * ga1.y + gb1.y);
    o2[(tid + 256) * 2 + 1] = __floats2half2_rn((v1.z - mean) * inv * ga1.z + gb1.z,
                                                (v1.w - mean) * inv * ga1.w + gb1.w);
}

__global__ void __launch_bounds__(256) ln2048_f16in(
    const __half* __restrict__ x, const float* __restrict__ g,
    const float* __restrict__ b, __half* __restrict__ out)
{
    constexpr int D = 2048;
    const int row = blockIdx.x;
    const int tid = threadIdx.x;
    const uint2* xr = reinterpret_cast<const uint2*>(x + (size_t)row * D);
    uint2 u0 = xr[tid];
    uint2 u1 = xr[tid + 256];
    float2 a0 = __half22float2(*reinterpret_cast<__half2*>(&u0.x));
    float2 a1 = __half22float2(*reinterpret_cast<__half2*>(&u0.y));
    float2 a2 = __half22float2(*reinterpret_cast<__half2*>(&u1.x));
    float2 a3 = __half22float2(*reinterpret_cast<__half2*>(&u1.y));

    float s  = a0.x + a0.y + a1.x + a1.y + a2.x + a2.y + a3.x + a3.y;
    float ss = a0.x*a0.x + a0.y*a0.y + a1.x*a1.x + a1.y*a1.y
             + a2.x*a2.x + a2.y*a2.y + a3.x*a3.x + a3.y*a3.y;
    #pragma unroll
    for (int o = 16; o > 0; o >>= 1) {
        s  += __shfl_xor_sync(0xFFFFFFFFu, s,  o);
        ss += __shfl_xor_sync(0xFFFFFFFFu, ss, o);
    }
    __shared__ float sh_s[8], sh_ss[8];
    if ((tid & 31) == 0) { sh_s[tid >> 5] = s; sh_ss[tid >> 5] = ss; }
    __syncthreads();
    float ts = 0.f, tss = 0.f;
    #pragma unroll
    for (int i = 0; i < 8; i++) { ts += sh_s[i]; tss += sh_ss[i]; }
    const float mean = ts * (1.0f / D);
    const float inv  = rsqrtf(tss * (1.0f / D) - mean * mean + 1e-5f);

    const float4* g4 = reinterpret_cast<const float4*>(g);
    const float4* b4 = reinterpret_cast<const float4*>(b);
    __half2* o2 = reinterpret_cast<__half2*>(out + (size_t)row * D);
    float4 ga0 = g4[tid],       gb0 = b4[tid];
    float4 ga1 = g4[tid + 256], gb1 = b4[tid + 256];
    o2[tid * 2]     = __floats2half2_rn((a0.x - mean) * inv * ga0.x + gb0.x,
                                        (a0.y - mean) * inv * ga0.y + gb0.y);
    o2[tid * 2 + 1] = __floats2half2_rn((a1.x - mean) * inv * ga0.z + gb0.z,
                                        (a1.y - mean) * inv * ga0.w + gb0.w);
    o2[(tid + 256) * 2]     = __floats2half2_rn((a2.x - mean) * inv * ga1.x + gb1.x,
                                                (a2.y - mean) * inv * ga1.y + gb1.y);
    o2[(tid + 256) * 2 + 1] = __floats2half2_rn((a3.x - mean) * inv * ga1.z + gb1.z,
                                                (a3.y - mean) * inv * ga1.w + gb1.w);
}

// ---------------------------------------------------------------------------
// Converts + transpose + bias prep
// ---------------------------------------------------------------------------
__device__ __forceinline__ void cvt4(const float* s, __half* d, int i) {
    float4 v = *reinterpret_cast<const float4*>(s + i);
    *reinterpret_cast<__half2*>(d + i)     = __floats2half2_rn(v.x, v.y);
    *reinterpret_cast<__half2*>(d + i + 2) = __floats2half2_rn(v.z, v.w);
}
__global__ void __launch_bounds__(256) cvtAll(
    const float* s0, __half* d0, int n0,
    const float* s1, __half* d1, int n1,
    const float* s2, __half* d2, int n2,
    const float* s3, __half* d3, int n3,
    const float* s4, __half* d4, int n4)
{
    int i = (blockIdx.x * 256 + threadIdx.x) * 4;
    if (i < n0) { cvt4(s0, d0, i); return; }  i -= n0;
    if (i < n1) { cvt4(s1, d1, i); return; }  i -= n1;
    if (i < n2) { cvt4(s2, d2, i); return; }  i -= n2;
    if (i < n3) { cvt4(s3, d3, i); return; }  i -= n3;
    if (i < n4) { cvt4(s4, d4, i); }
}

// Wv [n][k] fp32  ->  WvT [k][n] fp16
__global__ void __launch_bounds__(256) tranWv(
    const float* __restrict__ src, __half* __restrict__ dst)
{
    __shared__ float tile[32][33];
    const int tx = threadIdx.x, ty = threadIdx.y;
    const int x = blockIdx.x * 32 + tx;
    const int y = blockIdx.y * 32 + ty;
    #pragma unroll
    for (int jj = 0; jj < 32; jj += 8)
        tile[ty + jj][tx] = src[(size_t)(y + jj) * D_MODEL + x];
    __syncthreads();
    const int x2 = blockIdx.y * 32 + tx;
    const int y2 = blockIdx.x * 32 + ty;
    #pragma unroll
    for (int jj = 0; jj < 32; jj += 8)
        dst[(size_t)(y2 + jj) * D_MODEL + x2] = __float2half_rn(tile[tx][ty + jj]);
}

// bvo[m] = sum_n out_w[m][n]*bv[n] + out_b[m]
__global__ void __launch_bounds__(256) biasPrep(
    const float* __restrict__ out_w, const float* __restrict__ bv,
    const float* __restrict__ out_b, float* __restrict__ bvo)
{
    const int warp = threadIdx.x >> 5;
    const int lane = threadIdx.x & 31;
    const int m = blockIdx.x * 8 + warp;
    const float* row = out_w + (size_t)m * D_MODEL;
    float s = 0.f;
    for (int k = lane; k < D_MODEL; k += 32) s += row[k] * bv[k];
    #pragma unroll
    for (int o = 16; o > 0; o >>= 1) s += __shfl_xor_sync(0xFFFFFFFFu, s, o);
    if (lane == 0) bvo[m] = s + out_b[m];
}

// ---------------------------------------------------------------------------
extern "C" void kernel_launch(void* const* d_in, const int* in_sizes, int n_in,
                              void* d_out, int out_size)
{
    const float* x_t    = (const float*)d_in[0];
    const float* h_prev = (const float*)d_in[1];
    const float* W_proj = (const float*)d_in[2];
    const float* b_proj = (const float*)d_in[3];
    const float* in_w   = (const float*)d_in[4];
    const float* in_b   = (const float*)d_in[5];
    const float* out_w  = (const float*)d_in[6];
    const float* out_b  = (const float*)d_in[7];
    const float* ln1_g  = (const float*)d_in[8];
    const float* ln1_b  = (const float*)d_in[9];
    const float* ln2_g  = (const float*)d_in[10];
    const float* ln2_b  = (const float*)d_in[11];
    const float* gate_a = (const float*)d_in[12];
    const float* gate_b = (const float*)d_in[13];
    const float* ffn_w1 = (const float*)d_in[14];
    const float* ffn_b1 = (const float*)d_in[15];
    const float* ffn_w2 = (const float*)d_in[16];
    const float* ffn_b2 = (const float*)d_in[17];
    float* out = (float*)d_out;

    float *phh, *pbvo, *pzb;
    __half *px16, *pxh, *pqn16, *py16, *pt16;
    __half *pwp, *pwvT, *pwo, *pwvo, *pw1, *pw2;
    cudaGetSymbolAddress((void**)&phh,   g_hhat);
    cudaGetSymbolAddress((void**)&pbvo,  g_bvo);
    cudaGetSymbolAddress((void**)&pzb,   g_zb);
    cudaGetSymbolAddress((void**)&px16,  g_x16);
    cudaGetSymbolAddress((void**)&pxh,   g_xh);
    cudaGetSymbolAddress((void**)&pqn16, g_qn16);
    cudaGetSymbolAddress((void**)&py16,  g_y16);
    cudaGetSymbolAddress((void**)&pt16,  g_t16);
    cudaGetSymbolAddress((void**)&pwp,   g_wp16);
    cudaGetSymbolAddress((void**)&pwvT,  g_wvT16);
    cudaGetSymbolAddress((void**)&pwo,   g_wo16);
    cudaGetSymbolAddress((void**)&pwvo,  g_wvo16);
    cudaGetSymbolAddress((void**)&pw1,   g_w1_16);
    cudaGetSymbolAddress((void**)&pw2,   g_w2_16);

    cudaFuncSetAttribute(gemm16<0,0,1>, cudaFuncAttributeMaxDynamicSharedMemorySize, GSMEM);
    cudaFuncSetAttribute(gemm16<1,1,0>, cudaFuncAttributeMaxDynamicSharedMemorySize, GSMEM);
    cudaFuncSetAttribute(gemm16<2,0,1>, cudaFuncAttributeMaxDynamicSharedMemorySize, GSMEM);
    cudaFuncSetAttribute(gemm16<3,1,0>, cudaFuncAttributeMaxDynamicSharedMemorySize, GSMEM);

    // launch 0: converts (Wp, Wo, W1, W2, x_t)
    const int nwp = D_MODEL * 1024;
    const int nwo = D_MODEL * D_MODEL;
    const int nw1 = D_FF * D_MODEL;
    const int nw2 = D_MODEL * D_FF;
    const int nx  = B_DIM * 1024;
    const int ntot = nwp + nwo + nw1 + nw2 + nx;
    cvtAll<<<(ntot / 4 + 255) / 256, 256>>>(
        W_proj, pwp, nwp,
        out_w, pwo, nwo,
        ffn_w1, pw1, nw1,
        ffn_w2, pw2, nw2,
        x_t, px16, nx);

    // launch 1: Wv transpose+convert
    {
        dim3 tb(32, 8);
        dim3 tg(D_MODEL / 32, D_MODEL / 32);
        tranWv<<<tg, tb>>>(in_w + (size_t)2 * D_MODEL * D_MODEL, pwvT);
    }
    // launch 2: bvo = out_w @ bv + out_b
    biasPrep<<<D_MODEL / 8, 256>>>(out_w, in_b + 2 * D_MODEL, out_b, pbvo);

    const dim3 blk(NTHR);
    const dim3 gD (D_MODEL / BN, B_DIM   / BM);   // 16 x 32
    const dim3 gW (D_MODEL / BN, D_MODEL / BM);   // 16 x 16
    const dim3 gF (D_FF    / BN, B_DIM   / BM);   // 64 x 32

    // launch 3: Wvo = Wo @ Wv   <-- global ncu index 5
    gemm16<0,0,1><<<gW, blk, GSMEM>>>(pwo, pwvT, pzb, nullptr, pwvo, nullptr,
                                      nullptr, nullptr, nullptr,
                                      D_MODEL, D_MODEL);
    // launch 4: G1
    gemm16<0,0,1><<<gD, blk, GSMEM>>>(px16, pwp, b_proj, nullptr, pxh, nullptr,
                                      nullptr, nullptr, nullptr, D_MODEL, 1024);
    // launch 5: L1
    ln2048_f16in<<<B_DIM, 256>>>(pxh, ln1_g, ln1_b, pqn16);
    // launch 6: G23 (gate epilogue)
    gemm16<1,1,0><<<gD, blk, GSMEM>>>(pqn16, pwvo, pbvo, phh, nullptr, nullptr,
                                      h_prev, gate_a, gate_b, D_MODEL, D_MODEL);
    // launch 7: L2
    ln2048_f32in<<<B_DIM, 256>>>(phh, ln2_g, ln2_b, py16);
    // launch 8: G4
    gemm16<2,0,1><<<gF, blk, GSMEM>>>(py16, pw1, ffn_b1, nullptr, pt16, nullptr,
                                      nullptr, nullptr, nullptr, D_FF, D_MODEL);
    // launch 9: G5 (dual fp32 store)
    float* out2 = (out_size >= 2 * B_DIM * D_MODEL) ? (out + (size_t)B_DIM * D_MODEL) : out;
    gemm16<3,1,0><<<gD, blk, GSMEM>>>(pt16, pw2, ffn_b2, out, nullptr, out2,
                                      phh, nullptr, nullptr, D_MODEL, D_FF);
}

// round 12
// speedup vs baseline: 1.0364x; 1.0364x over previous
#include <cuda_runtime.h>
#include <cuda_fp16.h>
#include <cstdint>
#include <cstddef>

// ---------------------------------------------------------------------------
// GTrXLCell round 12: round-10 champion GEMM (untouched) + launch packing.
//  - mma.sync tensor ceiling ~50% established (R8/R9/R11: invariant across
//    warp counts and smem traffic) => GEMM mainloop frozen.
//  - gemmDual: Wvo + G1 batched in one grid (one wave-tail instead of two),
//    with w1/w2 fp16 conversion as trailing blocks (fills idle tail slots).
//  - Upfront convert shrinks to wp/wo/x only.
// Wvo fusion kept: ctx = qn @ Wvo^T + bvo, Wvo = Wo@Wv, bvo = Wo@bv + out_b.
// ---------------------------------------------------------------------------

#define B_DIM     4096
#define D_MODEL   2048
#define D_FF      8192

__device__ float  g_hhat[(size_t)B_DIM * D_MODEL];
__device__ __half g_x16 [(size_t)B_DIM * 1024];
__device__ __half g_xh  [(size_t)B_DIM * D_MODEL];
__device__ __half g_qn16[(size_t)B_DIM * D_MODEL];
__device__ __half g_y16 [(size_t)B_DIM * D_MODEL];
__device__ __half g_t16 [(size_t)B_DIM * D_FF];
__device__ __half g_wp16 [(size_t)D_MODEL * 1024];
__device__ __half g_wvT16[(size_t)D_MODEL * D_MODEL];
__device__ __half g_wo16 [(size_t)D_MODEL * D_MODEL];
__device__ __half g_wvo16[(size_t)D_MODEL * D_MODEL];
__device__ float  g_bvo  [D_MODEL];
__device__ float  g_zb   [D_MODEL];
__device__ __half g_w1_16[(size_t)D_FF * D_MODEL];
__device__ __half g_w2_16[(size_t)D_MODEL * D_FF];

// ------------------------------ helpers -----------------------------------
__device__ __forceinline__ uint32_t smem_u32(const void* p) {
    uint32_t a;
    asm("{ .reg .u64 t; cvta.to.shared.u64 t, %1; cvt.u32.u64 %0, t; }"
        : "=r"(a) : "l"(p));
    return a;
}
__device__ __forceinline__ void cp16(uint32_t dst, const void* src) {
    asm volatile("cp.async.cg.shared.global [%0], [%1], 16;"
                 :: "r"(dst), "l"(src));
}
#define CP_COMMIT() asm volatile("cp.async.commit_group;" ::: "memory")
#define CP_WAIT1()  asm volatile("cp.async.wait_group 1;" ::: "memory")
#define CP_WAIT0()  asm volatile("cp.async.wait_group 0;" ::: "memory")

__device__ __forceinline__ void ldsm_x4(uint32_t& r0, uint32_t& r1,
                                        uint32_t& r2, uint32_t& r3, uint32_t addr) {
    asm volatile("ldmatrix.sync.aligned.m8n8.x4.shared.b16 {%0,%1,%2,%3}, [%4];"
                 : "=r"(r0), "=r"(r1), "=r"(r2), "=r"(r3) : "r"(addr));
}
__device__ __forceinline__ void mma_f16(float c[4], const uint32_t a[4],
                                        const uint32_t b[2]) {
    asm volatile(
        "mma.sync.aligned.m16n8k16.row.col.f32.f16.f16.f32 "
        "{%0,%1,%2,%3}, {%4,%5,%6,%7}, {%8,%9}, {%0,%1,%2,%3};\n"
        : "+f"(c[0]), "+f"(c[1]), "+f"(c[2]), "+f"(c[3])
        : "r"(a[0]), "r"(a[1]), "r"(a[2]), "r"(a[3]), "r"(b[0]), "r"(b[1]));
}
__device__ __forceinline__ float sigmoidf_(float x) { return 1.0f / (1.0f + expf(-x)); }
__device__ __forceinline__ float gelu_exact(float x) {
    return 0.5f * x * (1.0f + erff(x * 0.70710678118654752f));
}

// ---------------------------------------------------------------------------
// fp16 GEMM (round-8/10 champion, UNTOUCHED): C = A @ Bw^T + bias (+epilogue).
// BM=BN=128, BK=64 halves, 3-stage cp.async ring, 1 barrier/ktile, occ=2,
// 256 threads = 8 warps (2x4), warp tile 64x32.
// ---------------------------------------------------------------------------
constexpr int BM = 128, BN = 128, BKH = 64;
constexpr int LDT = 72;
constexpr int TILE_A = BM * LDT;                               // 9216 halves
constexpr uint32_t STAGE_BYTES = 2u * (uint32_t)TILE_A * 2u;   // 36864 B
constexpr int STAGES = 3;
constexpr uint32_t GSMEM = STAGES * STAGE_BYTES;               // 110592 B

template <int MODE, int OUT32, int OUT16>
__global__ void __launch_bounds__(256, 2) gemm16(
    const __half* __restrict__ A, const __half* __restrict__ Bw,
    const float* __restrict__ bias,
    float* __restrict__ C32, __half* __restrict__ C16, float* __restrict__ C32b,
    const float* __restrict__ aux,
    const float* __restrict__ ga, const float* __restrict__ gb,
    int N, int K)
{
    extern __shared__ char smraw[];
    const uint32_t sbase = smem_u32(smraw);

    const int tid  = threadIdx.x;
    const int warp = tid >> 5;
    const int lane = tid & 31;
    const int wm = warp >> 2;
    const int wn = warp & 3;
    const int gr = lane >> 2;
    const int tg = lane & 3;

    const int block_row = blockIdx.y * BM;
    const int block_col = blockIdx.x * BN;
    const int KT = K / BKH;

    const int r0   = tid >> 3;
    const int scol = (tid & 7) * 8;
    const __half* Agp[4];
    const __half* Bgp[4];
    uint32_t dA[4], dB[4];
    #pragma unroll
    for (int k = 0; k < 4; k++) {
        const int rw = r0 + 32 * k;
        Agp[k] = A  + (size_t)(block_row + rw) * K + scol;
        Bgp[k] = Bw + (size_t)(block_col + rw) * K + scol;
        dA[k] = (uint32_t)(rw * LDT + scol) * 2u;
        dB[k] = (uint32_t)(TILE_A + rw * LDT + scol) * 2u;
    }

    const int j = lane >> 3, r = lane & 7;
    uint32_t aoff[4], boff[2];
    #pragma unroll
    for (int mi = 0; mi < 4; mi++)
        aoff[mi] = (uint32_t)(((wm * 64 + mi * 16 + (j & 1) * 8 + r) * LDT
                               + (j >> 1) * 8) * 2);
    #pragma unroll
    for (int n2 = 0; n2 < 2; n2++)
        boff[n2] = (uint32_t)((TILE_A
                               + (wn * 32 + n2 * 16 + (j >> 1) * 8 + r) * LDT
                               + (j & 1) * 8) * 2);

    float acc[4][4][4];
    #pragma unroll
    for (int mi = 0; mi < 4; mi++)
        #pragma unroll
        for (int ni = 0; ni < 4; ni++)
            #pragma unroll
            for (int q = 0; q < 4; q++) acc[mi][ni][q] = 0.0f;

    auto stage_fill = [&](int kt, int st) {
        const uint32_t sb = sbase + (uint32_t)st * STAGE_BYTES;
        const size_t ko = (size_t)kt * BKH;
        #pragma unroll
        for (int k = 0; k < 4; k++) cp16(sb + dA[k], Agp[k] + ko);
        #pragma unroll
        for (int k = 0; k < 4; k++) cp16(sb + dB[k], Bgp[k] + ko);
        CP_COMMIT();
    };

    stage_fill(0, 0);
    if (KT > 1) stage_fill(1, 1);

    for (int kt = 0; kt < KT; kt++) {
        if (kt + 1 < KT) CP_WAIT1(); else CP_WAIT0();
        __syncthreads();
        if (kt + 2 < KT) {
            int st = (kt + 2) % STAGES;
            stage_fill(kt + 2, st);
        }

        const uint32_t sb = sbase + (uint32_t)(kt % STAGES) * STAGE_BYTES;
        #pragma unroll
        for (int ks = 0; ks < 4; ks++) {
            const uint32_t kk = ks * 32;
            uint32_t af[4][4];
            #pragma unroll
            for (int mi = 0; mi < 4; mi++)
                ldsm_x4(af[mi][0], af[mi][1], af[mi][2], af[mi][3],
                        sb + aoff[mi] + kk);
            uint32_t bf[4][2];
            #pragma unroll
            for (int n2 = 0; n2 < 2; n2++) {
                uint32_t b0, b1, b2, b3;
                ldsm_x4(b0, b1, b2, b3, sb + boff[n2] + kk);
                bf[n2 * 2][0] = b0; bf[n2 * 2][1] = b1;
                bf[n2 * 2 + 1][0] = b2; bf[n2 * 2 + 1][1] = b3;
            }
            #pragma unroll
            for (int mi = 0; mi < 4; mi++)
                #pragma unroll
                for (int ni = 0; ni < 4; ni++)
                    mma_f16(acc[mi][ni], af[mi], bf[ni]);
        }
    }

    // epilogue
    #pragma unroll
    for (int mi = 0; mi < 4; mi++) {
        #pragma unroll
        for (int ni = 0; ni < 4; ni++) {
            const int col = block_col + wn * 32 + ni * 8 + 2 * tg;
            const float b0 = bias[col], b1 = bias[col + 1];
            float sa0 = 0.f, sa1 = 0.f, sb0 = 0.f, sb1 = 0.f;
            if (MODE == 1) {
                sa0 = sigmoidf_(ga[col]);     sa1 = sigmoidf_(ga[col + 1]);
                sb0 = sigmoidf_(gb[col]);     sb1 = sigmoidf_(gb[col + 1]);
            }
            #pragma unroll
            for (int h = 0; h < 2; h++) {
                const int row = block_row + wm * 64 + mi * 16 + gr + h * 8;
                float v0 = acc[mi][ni][2 * h + 0] + b0;
                float v1 = acc[mi][ni][2 * h + 1] + b1;
                const size_t off = (size_t)row * N + col;
                if (MODE == 1) {
                    v0 = sa0 * aux[off]     + sb0 * v0;
                    v1 = sa1 * aux[off + 1] + sb1 * v1;
                } else if (MODE == 2) {
                    v0 = gelu_exact(v0);
                    v1 = gelu_exact(v1);
                } else if (MODE == 3) {
                    v0 += aux[off];
                    v1 += aux[off + 1];
                }
                if (OUT32) {
                    float2 o = make_float2(v0, v1);
                    *reinterpret_cast<float2*>(&C32[off]) = o;
                    if (MODE == 3) *reinterpret_cast<float2*>(&C32b[off]) = o;
                }
                if (OUT16)
                    *reinterpret_cast<__half2*>(&C16[off]) = __floats2half2_rn(v0, v1);
            }
        }
    }
}

// ---------------------------------------------------------------------------
// gemmDual: Wvo (256 tiles) + G1 (512 tiles) batched in one grid, plus w1/w2
// fp32->fp16 conversion as trailing blocks (fill the GEMM drain tail).
// GEMM body is a textual copy of the champion (MODE 0, fp16 out).
// ---------------------------------------------------------------------------
constexpr int DUAL_WVO_TILES = (D_MODEL / BN) * (D_MODEL / BM);   // 256
constexpr int DUAL_G1_TILES  = (D_MODEL / BN) * (B_DIM / BM);     // 512
constexpr int DUAL_GEMM_BLKS = DUAL_WVO_TILES + DUAL_G1_TILES;    // 768
constexpr int CVT_ELEMS_PER_BLK = 8192;                            // 256 thr * 4 * 8
constexpr int DUAL_CVT_BLKS  = (2 * D_FF * D_MODEL) / CVT_ELEMS_PER_BLK;  // 4096
constexpr int DUAL_BLKS      = DUAL_GEMM_BLKS + DUAL_CVT_BLKS;

__device__ __forceinline__ void cvt4d(const float* s, __half* d, int i) {
    float4 v = *reinterpret_cast<const float4*>(s + i);
    *reinterpret_cast<__half2*>(d + i)     = __floats2half2_rn(v.x, v.y);
    *reinterpret_cast<__half2*>(d + i + 2) = __floats2half2_rn(v.z, v.w);
}

__global__ void __launch_bounds__(256, 2) gemmDual(
    const __half* __restrict__ Aw,  const __half* __restrict__ Bww,
    const float* __restrict__ biasw, __half* __restrict__ Cw,
    const __half* __restrict__ Ag,  const __half* __restrict__ Bwg,
    const float* __restrict__ biasg, __half* __restrict__ Cg,
    const float* __restrict__ s1, __half* __restrict__ d1, int n1,
    const float* __restrict__ s2, __half* __restrict__ d2)
{
    const int bid = blockIdx.x;

    // -------- trailing cvt blocks --------
    if (bid >= DUAL_GEMM_BLKS) {
        const int cb = bid - DUAL_GEMM_BLKS;
        const int tid = threadIdx.x;
        const int base = cb * CVT_ELEMS_PER_BLK;
        #pragma unroll
        for (int jj = 0; jj < 8; jj++) {
            const int i = base + (jj * 256 + tid) * 4;
            if (i < n1) cvt4d(s1, d1, i);
            else        cvt4d(s2, d2, i - n1);
        }
        return;
    }

    // -------- GEMM blocks: select param set --------
    const __half* A;  const __half* Bw;  const float* bias;  __half* C16;
    int bx, by, K;
    if (bid < DUAL_WVO_TILES) {
        A = Aw; Bw = Bww; bias = biasw; C16 = Cw; K = D_MODEL;
        bx = bid & 15; by = bid >> 4;
    } else {
        const int g = bid - DUAL_WVO_TILES;
        A = Ag; Bw = Bwg; bias = biasg; C16 = Cg; K = 1024;
        bx = g & 15; by = g >> 4;
    }
    const int N = D_MODEL;

    extern __shared__ char smraw[];
    const uint32_t sbase = smem_u32(smraw);

    const int tid  = threadIdx.x;
    const int warp = tid >> 5;
    const int lane = tid & 31;
    const int wm = warp >> 2;
    const int wn = warp & 3;
    const int gr = lane >> 2;
    const int tg = lane & 3;

    const int block_row = by * BM;
    const int block_col = bx * BN;
    const int KT = K / BKH;

    const int r0   = tid >> 3;
    const int scol = (tid & 7) * 8;
    const __half* Agp[4];
    const __half* Bgp[4];
    uint32_t dA[4], dB[4];
    #pragma unroll
    for (int k = 0; k < 4; k++) {
        const int rw = r0 + 32 * k;
        Agp[k] = A  + (size_t)(block_row + rw) * K + scol;
        Bgp[k] = Bw + (size_t)(block_col + rw) * K + scol;
        dA[k] = (uint32_t)(rw * LDT + scol) * 2u;
        dB[k] = (uint32_t)(TILE_A + rw * LDT + scol) * 2u;
    }

    const int j = lane >> 3, r = lane & 7;
    uint32_t aoff[4], boff[2];
    #pragma unroll
    for (int mi = 0; mi < 4; mi++)
        aoff[mi] = (uint32_t)(((wm * 64 + mi * 16 + (j & 1) * 8 + r) * LDT
                               + (j >> 1) * 8) * 2);
    #pragma unroll
    for (int n2 = 0; n2 < 2; n2++)
        boff[n2] = (uint32_t)((TILE_A
                               + (wn * 32 + n2 * 16 + (j >> 1) * 8 + r) * LDT
                               + (j & 1) * 8) * 2);

    float acc[4][4][4];
    #pragma unroll
    for (int mi = 0; mi < 4; mi++)
        #pragma unroll
        for (int ni = 0; ni < 4; ni++)
            #pragma unroll
            for (int q = 0; q < 4; q++) acc[mi][ni][q] = 0.0f;

    auto stage_fill = [&](int kt, int st) {
        const uint32_t sb = sbase + (uint32_t)st * STAGE_BYTES;
        const size_t ko = (size_t)kt * BKH;
        #pragma unroll
        for (int k = 0; k < 4; k++) cp16(sb + dA[k], Agp[k] + ko);
        #pragma unroll
        for (int k = 0; k < 4; k++) cp16(sb + dB[k], Bgp[k] + ko);
        CP_COMMIT();
    };

    stage_fill(0, 0);
    if (KT > 1) stage_fill(1, 1);

    for (int kt = 0; kt < KT; kt++) {
        if (kt + 1 < KT) CP_WAIT1(); else CP_WAIT0();
        __syncthreads();
        if (kt + 2 < KT) {
            int st = (kt + 2) % STAGES;
            stage_fill(kt + 2, st);
        }

        const uint32_t sb = sbase + (uint32_t)(kt % STAGES) * STAGE_BYTES;
        #pragma unroll
        for (int ks = 0; ks < 4; ks++) {
            const uint32_t kk = ks * 32;
            uint32_t af[4][4];
            #pragma unroll
            for (int mi = 0; mi < 4; mi++)
                ldsm_x4(af[mi][0], af[mi][1], af[mi][2], af[mi][3],
                        sb + aoff[mi] + kk);
            uint32_t bf[4][2];
            #pragma unroll
            for (int n2 = 0; n2 < 2; n2++) {
                uint32_t b0, b1, b2, b3;
                ldsm_x4(b0, b1, b2, b3, sb + boff[n2] + kk);
                bf[n2 * 2][0] = b0; bf[n2 * 2][1] = b1;
                bf[n2 * 2 + 1][0] = b2; bf[n2 * 2 + 1][1] = b3;
            }
            #pragma unroll
            for (int mi = 0; mi < 4; mi++)
                #pragma unroll
                for (int ni = 0; ni < 4; ni++)
                    mma_f16(acc[mi][ni], af[mi], bf[ni]);
        }
    }

    #pragma unroll
    for (int mi = 0; mi < 4; mi++) {
        #pragma unroll
        for (int ni = 0; ni < 4; ni++) {
            const int col = block_col + wn * 32 + ni * 8 + 2 * tg;
            const float b0 = bias[col], b1 = bias[col + 1];
            #pragma unroll
            for (int h = 0; h < 2; h++) {
                const int row = block_row + wm * 64 + mi * 16 + gr + h * 8;
                const float v0 = acc[mi][ni][2 * h + 0] + b0;
                const float v1 = acc[mi][ni][2 * h + 1] + b1;
                const size_t off = (size_t)row * N + col;
                *reinterpret_cast<__half2*>(&C16[off]) = __floats2half2_rn(v0, v1);
            }
        }
    }
}

// ---------------------------------------------------------------------------
// LayerNorm D=2048
// ---------------------------------------------------------------------------
__global__ void __launch_bounds__(256) ln2048_f32in(
    const float* __restrict__ x, const float* __restrict__ g,
    const float* __restrict__ b, __half* __restrict__ out)
{
    constexpr int D = 2048;
    const int row = blockIdx.x;
    const int tid = threadIdx.x;
    const float4* xr = reinterpret_cast<const float4*>(x + (size_t)row * D);

    float4 v0 = xr[tid];
    float4 v1 = xr[tid + 256];
    float s  = v0.x + v0.y + v0.z + v0.w + v1.x + v1.y + v1.z + v1.w;
    float ss = v0.x*v0.x + v0.y*v0.y + v0.z*v0.z + v0.w*v0.w
             + v1.x*v1.x + v1.y*v1.y + v1.z*v1.z + v1.w*v1.w;
    #pragma unroll
    for (int o = 16; o > 0; o >>= 1) {
        s  += __shfl_xor_sync(0xFFFFFFFFu, s,  o);
        ss += __shfl_xor_sync(0xFFFFFFFFu, ss, o);
    }
    __shared__ float sh_s[8], sh_ss[8];
    if ((tid & 31) == 0) { sh_s[tid >> 5] = s; sh_ss[tid >> 5] = ss; }
    __syncthreads();
    float ts = 0.f, tss = 0.f;
    #pragma unroll
    for (int i = 0; i < 8; i++) { ts += sh_s[i]; tss += sh_ss[i]; }
    const float mean = ts * (1.0f / D);
    const float inv  = rsqrtf(tss * (1.0f / D) - mean * mean + 1e-5f);

    const float4* g4 = reinterpret_cast<const float4*>(g);
    const float4* b4 = reinterpret_cast<const float4*>(b);
    __half2* o2 = reinterpret_cast<__half2*>(out + (size_t)row * D);
    float4 ga0 = g4[tid],       gb0 = b4[tid];
    float4 ga1 = g4[tid + 256], gb1 = b4[tid + 256];
    o2[tid * 2]     = __floats2half2_rn((v0.x - mean) * inv * ga0.x + gb0.x,
                                        (v0.y - mean) * inv * ga0.y + gb0.y);
    o2[tid * 2 + 1] = __floats2half2_rn((v0.z - mean) * inv * ga0.z + gb0.z,
                                        (v0.w - mean) * inv * ga0.w + gb0.w);
    o2[(tid + 256) * 2]     = __floats2half2_rn((v1.x - mean) * inv * ga1.x + gb1.x,
                                                (v1.y - mean) * inv * ga1.y + gb1.y);
    o2[(tid + 256) * 2 + 1] = __floats2half2_rn((v1.z - mean) * inv * ga1.z + gb1.z,
                                                (v1.w - mean) * inv * ga1.w + gb1.w);
}

__global__ void __launch_bounds__(256) ln2048_f16in(
    const __half* __restrict__ x, const float* __restrict__ g,
    const float* __restrict__ b, __half* __restrict__ out)
{
    constexpr int D = 2048;
    const int row = blockIdx.x;
    const int tid = threadIdx.x;
    const uint2* xr = reinterpret_cast<const uint2*>(x + (size_t)row * D);
    uint2 u0 = xr[tid];
    uint2 u1 = xr[tid + 256];
    float2 a0 = __half22float2(*reinterpret_cast<__half2*>(&u0.x));
    float2 a1 = __half22float2(*reinterpret_cast<__half2*>(&u0.y));
    float2 a2 = __half22float2(*reinterpret_cast<__half2*>(&u1.x));
    float2 a3 = __half22float2(*reinterpret_cast<__half2*>(&u1.y));

    float s  = a0.x + a0.y + a1.x + a1.y + a2.x + a2.y + a3.x + a3.y;
    float ss = a0.x*a0.x + a0.y*a0.y + a1.x*a1.x + a1.y*a1.y
             + a2.x*a2.x + a2.y*a2.y + a3.x*a3.x + a3.y*a3.y;
    #pragma unroll
    for (int o = 16; o > 0; o >>= 1) {
        s  += __shfl_xor_sync(0xFFFFFFFFu, s,  o);
        ss += __shfl_xor_sync(0xFFFFFFFFu, ss, o);
    }
    __shared__ float sh_s[8], sh_ss[8];
    if ((tid & 31) == 0) { sh_s[tid >> 5] = s; sh_ss[tid >> 5] = ss; }
    __syncthreads();
    float ts = 0.f, tss = 0.f;
    #pragma unroll
    for (int i = 0; i < 8; i++) { ts += sh_s[i]; tss += sh_ss[i]; }
    const float mean = ts * (1.0f / D);
    const float inv  = rsqrtf(tss * (1.0f / D) - mean * mean + 1e-5f);

    const float4* g4 = reinterpret_cast<const float4*>(g);
    const float4* b4 = reinterpret_cast<const float4*>(b);
    __half2* o2 = reinterpret_cast<__half2*>(out + (size_t)row * D);
    float4 ga0 = g4[tid],       gb0 = b4[tid];
    float4 ga1 = g4[tid + 256], gb1 = b4[tid + 256];
    o2[tid * 2]     = __floats2half2_rn((a0.x - mean) * inv * ga0.x + gb0.x,
                                        (a0.y - mean) * inv * ga0.y + gb0.y);
    o2[tid * 2 + 1] = __floats2half2_rn((a1.x - mean) * inv * ga0.z + gb0.z,
                                        (a1.y - mean) * inv * ga0.w + gb0.w);
    o2[(tid + 256) * 2]     = __floats2half2_rn((a2.x - mean) * inv * ga1.x + gb1.x,
                                                (a2.y - mean) * inv * ga1.y + gb1.y);
    o2[(tid + 256) * 2 + 1] = __floats2half2_rn((a3.x - mean) * inv * ga1.z + gb1.z,
                                                (a3.y - mean) * inv * ga1.w + gb1.w);
}

// ---------------------------------------------------------------------------
// Upfront converts (wp, wo, x_t) + transpose + bias prep
// ---------------------------------------------------------------------------
__global__ void __launch_bounds__(256) cvt3(
    const float* s0, __half* d0, int n0,
    const float* s1, __half* d1, int n1,
    const float* s2, __half* d2, int n2)
{
    int i = (blockIdx.x * 256 + threadIdx.x) * 4;
    if (i < n0) { cvt4d(s0, d0, i); return; }  i -= n0;
    if (i < n1) { cvt4d(s1, d1, i); return; }  i -= n1;
    if (i < n2) { cvt4d(s2, d2, i); }
}

// Wv [n][k] fp32  ->  WvT [k][n] fp16
__global__ void __launch_bounds__(256) tranWv(
    const float* __restrict__ src, __half* __restrict__ dst)
{
    __shared__ float tile[32][33];
    const int tx = threadIdx.x, ty = threadIdx.y;
    const int x = blockIdx.x * 32 + tx;
    const int y = blockIdx.y * 32 + ty;
    #pragma unroll
    for (int jj = 0; jj < 32; jj += 8)
        tile[ty + jj][tx] = src[(size_t)(y + jj) * D_MODEL + x];
    __syncthreads();
    const int x2 = blockIdx.y * 32 + tx;
    const int y2 = blockIdx.x * 32 + ty;
    #pragma unroll
    for (int jj = 0; jj < 32; jj += 8)
        dst[(size_t)(y2 + jj) * D_MODEL + x2] = __float2half_rn(tile[tx][ty + jj]);
}

// bvo[m] = sum_n out_w[m][n]*bv[n] + out_b[m]
__global__ void __launch_bounds__(256) biasPrep(
    const float* __restrict__ out_w, const float* __restrict__ bv,
    const float* __restrict__ out_b, float* __restrict__ bvo)
{
    const int warp = threadIdx.x >> 5;
    const int lane = threadIdx.x & 31;
    const int m = blockIdx.x * 8 + warp;
    const float* row = out_w + (size_t)m * D_MODEL;
    float s = 0.f;
    for (int k = lane; k < D_MODEL; k += 32) s += row[k] * bv[k];
    #pragma unroll
    for (int o = 16; o > 0; o >>= 1) s += __shfl_xor_sync(0xFFFFFFFFu, s, o);
    if (lane == 0) bvo[m] = s + out_b[m];
}

// ---------------------------------------------------------------------------
extern "C" void kernel_launch(void* const* d_in, const int* in_sizes, int n_in,
                              void* d_out, int out_size)
{
    const float* x_t    = (const float*)d_in[0];
    const float* h_prev = (const float*)d_in[1];
    const float* W_proj = (const float*)d_in[2];
    const float* b_proj = (const float*)d_in[3];
    const float* in_w   = (const float*)d_in[4];
    const float* in_b   = (const float*)d_in[5];
    const float* out_w  = (const float*)d_in[6];
    const float* out_b  = (const float*)d_in[7];
    const float* ln1_g  = (const float*)d_in[8];
    const float* ln1_b  = (const float*)d_in[9];
    const float* ln2_g  = (const float*)d_in[10];
    const float* ln2_b  = (const float*)d_in[11];
    const float* gate_a = (const float*)d_in[12];
    const float* gate_b = (const float*)d_in[13];
    const float* ffn_w1 = (const float*)d_in[14];
    const float* ffn_b1 = (const float*)d_in[15];
    const float* ffn_w2 = (const float*)d_in[16];
    const float* ffn_b2 = (const float*)d_in[17];
    float* out = (float*)d_out;

    float *phh, *pbvo, *pzb;
    __half *px16, *pxh, *pqn16, *py16, *pt16;
    __half *pwp, *pwvT, *pwo, *pwvo, *pw1, *pw2;
    cudaGetSymbolAddress((void**)&phh,   g_hhat);
    cudaGetSymbolAddress((void**)&pbvo,  g_bvo);
    cudaGetSymbolAddress((void**)&pzb,   g_zb);
    cudaGetSymbolAddress((void**)&px16,  g_x16);
    cudaGetSymbolAddress((void**)&pxh,   g_xh);
    cudaGetSymbolAddress((void**)&pqn16, g_qn16);
    cudaGetSymbolAddress((void**)&py16,  g_y16);
    cudaGetSymbolAddress((void**)&pt16,  g_t16);
    cudaGetSymbolAddress((void**)&pwp,   g_wp16);
    cudaGetSymbolAddress((void**)&pwvT,  g_wvT16);
    cudaGetSymbolAddress((void**)&pwo,   g_wo16);
    cudaGetSymbolAddress((void**)&pwvo,  g_wvo16);
    cudaGetSymbolAddress((void**)&pw1,   g_w1_16);
    cudaGetSymbolAddress((void**)&pw2,   g_w2_16);

    cudaFuncSetAttribute(gemm16<1,1,0>, cudaFuncAttributeMaxDynamicSharedMemorySize, GSMEM);
    cudaFuncSetAttribute(gemm16<2,0,1>, cudaFuncAttributeMaxDynamicSharedMemorySize, GSMEM);
    cudaFuncSetAttribute(gemm16<3,1,0>, cudaFuncAttributeMaxDynamicSharedMemorySize, GSMEM);
    cudaFuncSetAttribute(gemmDual,      cudaFuncAttributeMaxDynamicSharedMemorySize, GSMEM);

    // launch 0: upfront converts (Wp, Wo, x_t)
    const int nwp = D_MODEL * 1024;
    const int nwo = D_MODEL * D_MODEL;
    const int nx  = B_DIM * 1024;
    const int nup = nwp + nwo + nx;
    cvt3<<<(nup / 4 + 255) / 256, 256>>>(
        W_proj, pwp, nwp,
        out_w, pwo, nwo,
        x_t, px16, nx);

    // launch 1: Wv transpose+convert
    {
        dim3 tb(32, 8);
        dim3 tg(D_MODEL / 32, D_MODEL / 32);
        tranWv<<<tg, tb>>>(in_w + (size_t)2 * D_MODEL * D_MODEL, pwvT);
    }
    // launch 2: bvo = out_w @ bv + out_b
    biasPrep<<<D_MODEL / 8, 256>>>(out_w, in_b + 2 * D_MODEL, out_b, pbvo);

    const dim3 blk(256);
    const dim3 gD (D_MODEL / BN, B_DIM / BM);   // 16 x 32
    const dim3 gF (D_FF    / BN, B_DIM / BM);   // 64 x 32

    // launch 3: gemmDual = Wvo + G1 + w1/w2 converts  <-- global ncu index 5
    gemmDual<<<DUAL_BLKS, blk, GSMEM>>>(
        pwo, pwvT, pzb, pwvo,                   // Wvo = Wo @ Wv
        px16, pwp, b_proj, pxh,                 // G1  = x16 @ Wp^T + b_proj
        ffn_w1, pw1, D_FF * D_MODEL,            // cvt w1
        ffn_w2, pw2);                           // cvt w2
    // launch 4: L1
    ln2048_f16in<<<B_DIM, 256>>>(pxh, ln1_g, ln1_b, pqn16);
    // launch 5: G23 (gate epilogue)
    gemm16<1,1,0><<<gD, blk, GSMEM>>>(pqn16, pwvo, pbvo, phh, nullptr, nullptr,
                                      h_prev, gate_a, gate_b, D_MODEL, D_MODEL);
    // launch 6: L2
    ln2048_f32in<<<B_DIM, 256>>>(phh, ln2_g, ln2_b, py16);
    // launch 7: G4
    gemm16<2,0,1><<<gF, blk, GSMEM>>>(py16, pw1, ffn_b1, nullptr, pt16, nullptr,
                                      nullptr, nullptr, nullptr, D_FF, D_MODEL);
    // launch 8: G5 (dual fp32 store)
    float* out2 = (out_size >= 2 * B_DIM * D_MODEL) ? (out + (size_t)B_DIM * D_MODEL) : out;
    gemm16<3,1,0><<<gD, blk, GSMEM>>>(pt16, pw2, ffn_b2, out, nullptr, out2,
                                      phh, nullptr, nullptr, D_MODEL, D_FF);
}

// round 13
// speedup vs baseline: 1.0523x; 1.0153x over previous
#include <cuda_runtime.h>
#include <cuda_fp16.h>
#include <cstdint>
#include <cstddef>

// ---------------------------------------------------------------------------
// GTrXLCell round 13: overlap re-balancing at the mma.sync roofline (~308TF/s).
//  - gemmDual: pure Wvo + G1 (768 blocks) -- cvt moved OUT.
//  - gemmGateCvt: G23 (512 blocks, 1.73 waves) + w1/w2 fp16 cvt as trailing
//    blocks (fills the 80 idle wave-2 slots; w1/w2 not needed until G4).
//  - prep: single launch = cvt(wp,wo,x) + WvT transpose + bvo bias prep.
// Champion GEMM mainloop byte-frozen since round 8.
// ---------------------------------------------------------------------------

#define B_DIM     4096
#define D_MODEL   2048
#define D_FF      8192

__device__ float  g_hhat[(size_t)B_DIM * D_MODEL];
__device__ __half g_x16 [(size_t)B_DIM * 1024];
__device__ __half g_xh  [(size_t)B_DIM * D_MODEL];
__device__ __half g_qn16[(size_t)B_DIM * D_MODEL];
__device__ __half g_y16 [(size_t)B_DIM * D_MODEL];
__device__ __half g_t16 [(size_t)B_DIM * D_FF];
__device__ __half g_wp16 [(size_t)D_MODEL * 1024];
__device__ __half g_wvT16[(size_t)D_MODEL * D_MODEL];
__device__ __half g_wo16 [(size_t)D_MODEL * D_MODEL];
__device__ __half g_wvo16[(size_t)D_MODEL * D_MODEL];
__device__ float  g_bvo  [D_MODEL];
__device__ float  g_zb   [D_MODEL];
__device__ __half g_w1_16[(size_t)D_FF * D_MODEL];
__device__ __half g_w2_16[(size_t)D_MODEL * D_FF];

// ------------------------------ helpers -----------------------------------
__device__ __forceinline__ uint32_t smem_u32(const void* p) {
    uint32_t a;
    asm("{ .reg .u64 t; cvta.to.shared.u64 t, %1; cvt.u32.u64 %0, t; }"
        : "=r"(a) : "l"(p));
    return a;
}
__device__ __forceinline__ void cp16(uint32_t dst, const void* src) {
    asm volatile("cp.async.cg.shared.global [%0], [%1], 16;"
                 :: "r"(dst), "l"(src));
}
#define CP_COMMIT() asm volatile("cp.async.commit_group;" ::: "memory")
#define CP_WAIT1()  asm volatile("cp.async.wait_group 1;" ::: "memory")
#define CP_WAIT0()  asm volatile("cp.async.wait_group 0;" ::: "memory")

__device__ __forceinline__ void ldsm_x4(uint32_t& r0, uint32_t& r1,
                                        uint32_t& r2, uint32_t& r3, uint32_t addr) {
    asm volatile("ldmatrix.sync.aligned.m8n8.x4.shared.b16 {%0,%1,%2,%3}, [%4];"
                 : "=r"(r0), "=r"(r1), "=r"(r2), "=r"(r3) : "r"(addr));
}
__device__ __forceinline__ void mma_f16(float c[4], const uint32_t a[4],
                                        const uint32_t b[2]) {
    asm volatile(
        "mma.sync.aligned.m16n8k16.row.col.f32.f16.f16.f32 "
        "{%0,%1,%2,%3}, {%4,%5,%6,%7}, {%8,%9}, {%0,%1,%2,%3};\n"
        : "+f"(c[0]), "+f"(c[1]), "+f"(c[2]), "+f"(c[3])
        : "r"(a[0]), "r"(a[1]), "r"(a[2]), "r"(a[3]), "r"(b[0]), "r"(b[1]));
}
__device__ __forceinline__ float sigmoidf_(float x) { return 1.0f / (1.0f + expf(-x)); }
__device__ __forceinline__ float gelu_exact(float x) {
    return 0.5f * x * (1.0f + erff(x * 0.70710678118654752f));
}
__device__ __forceinline__ void cvt4d(const float* s, __half* d, int i) {
    float4 v = *reinterpret_cast<const float4*>(s + i);
    *reinterpret_cast<__half2*>(d + i)     = __floats2half2_rn(v.x, v.y);
    *reinterpret_cast<__half2*>(d + i + 2) = __floats2half2_rn(v.z, v.w);
}

// ---------------------------------------------------------------------------
// Champion GEMM constants (frozen)
// ---------------------------------------------------------------------------
constexpr int BM = 128, BN = 128, BKH = 64;
constexpr int LDT = 72;
constexpr int TILE_A = BM * LDT;                               // 9216 halves
constexpr uint32_t STAGE_BYTES = 2u * (uint32_t)TILE_A * 2u;   // 36864 B
constexpr int STAGES = 3;
constexpr uint32_t GSMEM = STAGES * STAGE_BYTES;               // 110592 B

// Shared mainloop body (champion, unchanged): computes acc for (block_row,
// block_col) tile. Inlined into each kernel.
#define GEMM_MAINLOOP(A_, B_, K_, block_row_, block_col_)                      \
    const int tid  = threadIdx.x;                                             \
    const int warp = tid >> 5;                                                 \
    const int lane = tid & 31;                                                 \
    const int wm = warp >> 2;                                                  \
    const int wn = warp & 3;                                                   \
    const int gr = lane >> 2;                                                  \
    const int tg = lane & 3;                                                   \
    const int KT = (K_) / BKH;                                                 \
    const int r0   = tid >> 3;                                                 \
    const int scol = (tid & 7) * 8;                                            \
    const __half* Agp[4];                                                      \
    const __half* Bgp[4];                                                      \
    uint32_t dA[4], dB[4];                                                     \
    _Pragma("unroll")                                                          \
    for (int k = 0; k < 4; k++) {                                              \
        const int rw = r0 + 32 * k;                                            \
        Agp[k] = (A_) + (size_t)((block_row_) + rw) * (K_) + scol;             \
        Bgp[k] = (B_) + (size_t)((block_col_) + rw) * (K_) + scol;             \
        dA[k] = (uint32_t)(rw * LDT + scol) * 2u;                              \
        dB[k] = (uint32_t)(TILE_A + rw * LDT + scol) * 2u;                     \
    }                                                                          \
    const int j = lane >> 3, r = lane & 7;                                     \
    uint32_t aoff[4], boff[2];                                                 \
    _Pragma("unroll")                                                          \
    for (int mi = 0; mi < 4; mi++)                                             \
        aoff[mi] = (uint32_t)(((wm * 64 + mi * 16 + (j & 1) * 8 + r) * LDT     \
                               + (j >> 1) * 8) * 2);                           \
    _Pragma("unroll")                                                          \
    for (int n2 = 0; n2 < 2; n2++)                                             \
        boff[n2] = (uint32_t)((TILE_A                                          \
                               + (wn * 32 + n2 * 16 + (j >> 1) * 8 + r) * LDT  \
                               + (j & 1) * 8) * 2);                            \
    float acc[4][4][4];                                                        \
    _Pragma("unroll")                                                          \
    for (int mi = 0; mi < 4; mi++)                                             \
        _Pragma("unroll")                                                      \
        for (int ni = 0; ni < 4; ni++)                                         \
            _Pragma("unroll")                                                  \
            for (int q = 0; q < 4; q++) acc[mi][ni][q] = 0.0f;                 \
    auto stage_fill = [&](int kt, int st) {                                    \
        const uint32_t sb = sbase + (uint32_t)st * STAGE_BYTES;                \
        const size_t ko = (size_t)kt * BKH;                                    \
        _Pragma("unroll")                                                      \
        for (int k = 0; k < 4; k++) cp16(sb + dA[k], Agp[k] + ko);             \
        _Pragma("unroll")                                                      \
        for (int k = 0; k < 4; k++) cp16(sb + dB[k], Bgp[k] + ko);             \
        CP_COMMIT();                                                           \
    };                                                                         \
    stage_fill(0, 0);                                                          \
    if (KT > 1) stage_fill(1, 1);                                              \
    for (int kt = 0; kt < KT; kt++) {                                          \
        if (kt + 1 < KT) CP_WAIT1(); else CP_WAIT0();                          \
        __syncthreads();                                                       \
        if (kt + 2 < KT) {                                                     \
            int st = (kt + 2) % STAGES;                                        \
            stage_fill(kt + 2, st);                                            \
        }                                                                      \
        const uint32_t sb = sbase + (uint32_t)(kt % STAGES) * STAGE_BYTES;     \
        _Pragma("unroll")                                                      \
        for (int ks = 0; ks < 4; ks++) {                                       \
            const uint32_t kk = ks * 32;                                       \
            uint32_t af[4][4];                                                 \
            _Pragma("unroll")                                                  \
            for (int mi = 0; mi < 4; mi++)                                     \
                ldsm_x4(af[mi][0], af[mi][1], af[mi][2], af[mi][3],            \
                        sb + aoff[mi] + kk);                                   \
            uint32_t bf[4][2];                                                 \
            _Pragma("unroll")                                                  \
            for (int n2 = 0; n2 < 2; n2++) {                                   \
                uint32_t b0, b1, b2, b3;                                       \
                ldsm_x4(b0, b1, b2, b3, sb + boff[n2] + kk);                   \
                bf[n2 * 2][0] = b0; bf[n2 * 2][1] = b1;                        \
                bf[n2 * 2 + 1][0] = b2; bf[n2 * 2 + 1][1] = b3;                \
            }                                                                  \
            _Pragma("unroll")                                                  \
            for (int mi = 0; mi < 4; mi++)                                     \
                _Pragma("unroll")                                              \
                for (int ni = 0; ni < 4; ni++)                                 \
                    mma_f16(acc[mi][ni], af[mi], bf[ni]);                      \
        }                                                                      \
    }

// ---------------------------------------------------------------------------
// gemm16 template (for G4 gelu and G5 residual)
// ---------------------------------------------------------------------------
template <int MODE, int OUT32, int OUT16>
__global__ void __launch_bounds__(256, 2) gemm16(
    const __half* __restrict__ A, const __half* __restrict__ Bw,
    const float* __restrict__ bias,
    float* __restrict__ C32, __half* __restrict__ C16, float* __restrict__ C32b,
    const float* __restrict__ aux,
    const float* __restrict__ ga, const float* __restrict__ gb,
    int N, int K)
{
    extern __shared__ char smraw[];
    const uint32_t sbase = smem_u32(smraw);
    const int block_row = blockIdx.y * BM;
    const int block_col = blockIdx.x * BN;

    GEMM_MAINLOOP(A, Bw, K, block_row, block_col)

    #pragma unroll
    for (int mi = 0; mi < 4; mi++) {
        #pragma unroll
        for (int ni = 0; ni < 4; ni++) {
            const int col = block_col + wn * 32 + ni * 8 + 2 * tg;
            const float b0 = bias[col], b1 = bias[col + 1];
            float sa0 = 0.f, sa1 = 0.f, sb0 = 0.f, sb1 = 0.f;
            if (MODE == 1) {
                sa0 = sigmoidf_(ga[col]);     sa1 = sigmoidf_(ga[col + 1]);
                sb0 = sigmoidf_(gb[col]);     sb1 = sigmoidf_(gb[col + 1]);
            }
            #pragma unroll
            for (int h = 0; h < 2; h++) {
                const int row = block_row + wm * 64 + mi * 16 + gr + h * 8;
                float v0 = acc[mi][ni][2 * h + 0] + b0;
                float v1 = acc[mi][ni][2 * h + 1] + b1;
                const size_t off = (size_t)row * N + col;
                if (MODE == 1) {
                    v0 = sa0 * aux[off]     + sb0 * v0;
                    v1 = sa1 * aux[off + 1] + sb1 * v1;
                } else if (MODE == 2) {
                    v0 = gelu_exact(v0);
                    v1 = gelu_exact(v1);
                } else if (MODE == 3) {
                    v0 += aux[off];
                    v1 += aux[off + 1];
                }
                if (OUT32) {
                    float2 o = make_float2(v0, v1);
                    *reinterpret_cast<float2*>(&C32[off]) = o;
                    if (MODE == 3) *reinterpret_cast<float2*>(&C32b[off]) = o;
                }
                if (OUT16)
                    *reinterpret_cast<__half2*>(&C16[off]) = __floats2half2_rn(v0, v1);
            }
        }
    }
}

// ---------------------------------------------------------------------------
// gemmDual: Wvo (256 tiles) + G1 (512 tiles), pure GEMM (cvt moved to G23).
// ---------------------------------------------------------------------------
constexpr int DUAL_WVO_TILES = (D_MODEL / BN) * (D_MODEL / BM);   // 256
constexpr int DUAL_G1_TILES  = (D_MODEL / BN) * (B_DIM / BM);     // 512
constexpr int DUAL_BLKS      = DUAL_WVO_TILES + DUAL_G1_TILES;    // 768

__global__ void __launch_bounds__(256, 2) gemmDual(
    const __half* __restrict__ Aw,  const __half* __restrict__ Bww,
    const float* __restrict__ biasw, __half* __restrict__ Cw,
    const __half* __restrict__ Ag,  const __half* __restrict__ Bwg,
    const float* __restrict__ biasg, __half* __restrict__ Cg)
{
    const int bid = blockIdx.x;
    const __half* A;  const __half* Bw;  const float* bias;  __half* C16;
    int bx, by, K;
    if (bid < DUAL_WVO_TILES) {
        A = Aw; Bw = Bww; bias = biasw; C16 = Cw; K = D_MODEL;
        bx = bid & 15; by = bid >> 4;
    } else {
        const int g = bid - DUAL_WVO_TILES;
        A = Ag; Bw = Bwg; bias = biasg; C16 = Cg; K = 1024;
        bx = g & 15; by = g >> 4;
    }
    const int N = D_MODEL;

    extern __shared__ char smraw[];
    const uint32_t sbase = smem_u32(smraw);
    const int block_row = by * BM;
    const int block_col = bx * BN;

    GEMM_MAINLOOP(A, Bw, K, block_row, block_col)

    #pragma unroll
    for (int mi = 0; mi < 4; mi++) {
        #pragma unroll
        for (int ni = 0; ni < 4; ni++) {
            const int col = block_col + wn * 32 + ni * 8 + 2 * tg;
            const float b0 = bias[col], b1 = bias[col + 1];
            #pragma unroll
            for (int h = 0; h < 2; h++) {
                const int row = block_row + wm * 64 + mi * 16 + gr + h * 8;
                const float v0 = acc[mi][ni][2 * h + 0] + b0;
                const float v1 = acc[mi][ni][2 * h + 1] + b1;
                const size_t off = (size_t)row * N + col;
                *reinterpret_cast<__half2*>(&C16[off]) = __floats2half2_rn(v0, v1);
            }
        }
    }
}

// ---------------------------------------------------------------------------
// gemmGateCvt: G23 (512 gate-GEMM blocks) + w1/w2 cvt trailing blocks.
// ---------------------------------------------------------------------------
constexpr int GATE_GEMM_BLKS = (D_MODEL / BN) * (B_DIM / BM);     // 512
constexpr int CVT_ELEMS_PER_BLK = 8192;
constexpr int GATE_CVT_BLKS  = (2 * D_FF * D_MODEL) / CVT_ELEMS_PER_BLK;  // 4096
constexpr int GATE_BLKS      = GATE_GEMM_BLKS + GATE_CVT_BLKS;

__global__ void __launch_bounds__(256, 2) gemmGateCvt(
    const __half* __restrict__ A, const __half* __restrict__ Bw,
    const float* __restrict__ bias, float* __restrict__ C32,
    const float* __restrict__ aux,
    const float* __restrict__ ga, const float* __restrict__ gb,
    const float* __restrict__ s1, __half* __restrict__ d1, int n1,
    const float* __restrict__ s2, __half* __restrict__ d2)
{
    const int bid = blockIdx.x;

    if (bid >= GATE_GEMM_BLKS) {                 // trailing cvt blocks
        const int cb = bid - GATE_GEMM_BLKS;
        const int t  = threadIdx.x;
        const int base = cb * CVT_ELEMS_PER_BLK;
        #pragma unroll
        for (int jj = 0; jj < 8; jj++) {
            const int i = base + (jj * 256 + t) * 4;
            if (i < n1) cvt4d(s1, d1, i);
            else        cvt4d(s2, d2, i - n1);
        }
        return;
    }

    const int bx = bid & 15, by = bid >> 4;
    const int N = D_MODEL, K = D_MODEL;

    extern __shared__ char smraw[];
    const uint32_t sbase = smem_u32(smraw);
    const int block_row = by * BM;
    const int block_col = bx * BN;

    GEMM_MAINLOOP(A, Bw, K, block_row, block_col)

    #pragma unroll
    for (int mi = 0; mi < 4; mi++) {
        #pragma unroll
        for (int ni = 0; ni < 4; ni++) {
            const int col = block_col + wn * 32 + ni * 8 + 2 * tg;
            const float b0 = bias[col], b1 = bias[col + 1];
            const float sa0 = sigmoidf_(ga[col]),     sa1 = sigmoidf_(ga[col + 1]);
            const float sb0 = sigmoidf_(gb[col]),     sb1 = sigmoidf_(gb[col + 1]);
            #pragma unroll
            for (int h = 0; h < 2; h++) {
                const int row = block_row + wm * 64 + mi * 16 + gr + h * 8;
                const size_t off = (size_t)row * N + col;
                float v0 = sa0 * aux[off]     + sb0 * (acc[mi][ni][2 * h + 0] + b0);
                float v1 = sa1 * aux[off + 1] + sb1 * (acc[mi][ni][2 * h + 1] + b1);
                *reinterpret_cast<float2*>(&C32[off]) = make_float2(v0, v1);
            }
        }
    }
}

// ---------------------------------------------------------------------------
// prep: single launch = cvt(wp, wo, x_t) + WvT transpose + bvo bias prep.
// ---------------------------------------------------------------------------
constexpr int PREP_CVT_ELEMS = D_MODEL * 1024 + D_MODEL * D_MODEL + B_DIM * 1024;
constexpr int PREP_CVT_BLKS  = PREP_CVT_ELEMS / CVT_ELEMS_PER_BLK;       // 1280
constexpr int PREP_TRAN_BLKS = (D_MODEL / 32) * (D_MODEL / 32);          // 4096
constexpr int PREP_BIAS_BLKS = D_MODEL / 8;                              // 256
constexpr int PREP_BLKS = PREP_CVT_BLKS + PREP_TRAN_BLKS + PREP_BIAS_BLKS;

__global__ void __launch_bounds__(256) prep(
    const float* s0, __half* d0, int n0,      // W_proj
    const float* s1, __half* d1, int n1,      // out_w
    const float* s2, __half* d2, int n2,      // x_t
    const float* __restrict__ wvsrc, __half* __restrict__ wvTdst,
    const float* __restrict__ out_w, const float* __restrict__ bv,
    const float* __restrict__ out_b, float* __restrict__ bvo)
{
    const int bid = blockIdx.x;
    const int tid = threadIdx.x;

    if (bid < PREP_CVT_BLKS) {
        const int base = bid * CVT_ELEMS_PER_BLK;
        #pragma unroll
        for (int jj = 0; jj < 8; jj++) {
            int i = base + (jj * 256 + tid) * 4;
            if (i < n0)                { cvt4d(s0, d0, i); continue; }
            i -= n0;
            if (i < n1)                { cvt4d(s1, d1, i); continue; }
            i -= n1;
            if (i < n2)                { cvt4d(s2, d2, i); }
        }
        return;
    }

    if (bid < PREP_CVT_BLKS + PREP_TRAN_BLKS) {
        __shared__ float tile[32][33];
        const int b2 = bid - PREP_CVT_BLKS;
        const int bx = b2 & 63, by = b2 >> 6;
        const int tx = tid & 31, ty = tid >> 5;       // ty 0..7
        const int x = bx * 32 + tx;
        const int y = by * 32 + ty;
        #pragma unroll
        for (int jj = 0; jj < 32; jj += 8)
            tile[ty + jj][tx] = wvsrc[(size_t)(y + jj) * D_MODEL + x];
        __syncthreads();
        const int x2 = by * 32 + tx;
        const int y2 = bx * 32 + ty;
        #pragma unroll
        for (int jj = 0; jj < 32; jj += 8)
            wvTdst[(size_t)(y2 + jj) * D_MODEL + x2] =
                __float2half_rn(tile[tx][ty + jj]);
        return;
    }

    // bias prep: bvo[m] = out_w[m,:]·bv + out_b[m]
    const int b3 = bid - PREP_CVT_BLKS - PREP_TRAN_BLKS;
    const int warp = tid >> 5, lane = tid & 31;
    const int m = b3 * 8 + warp;
    const float* row = out_w + (size_t)m * D_MODEL;
    float s = 0.f;
    for (int k = lane; k < D_MODEL; k += 32) s += row[k] * bv[k];
    #pragma unroll
    for (int o = 16; o > 0; o >>= 1) s += __shfl_xor_sync(0xFFFFFFFFu, s, o);
    if (lane == 0) bvo[m] = s + out_b[m];
}

// ---------------------------------------------------------------------------
// LayerNorm D=2048
// ---------------------------------------------------------------------------
__global__ void __launch_bounds__(256) ln2048_f32in(
    const float* __restrict__ x, const float* __restrict__ g,
    const float* __restrict__ b, __half* __restrict__ out)
{
    constexpr int D = 2048;
    const int row = blockIdx.x;
    const int tid = threadIdx.x;
    const float4* xr = reinterpret_cast<const float4*>(x + (size_t)row * D);

    float4 v0 = xr[tid];
    float4 v1 = xr[tid + 256];
    float s  = v0.x + v0.y + v0.z + v0.w + v1.x + v1.y + v1.z + v1.w;
    float ss = v0.x*v0.x + v0.y*v0.y + v0.z*v0.z + v0.w*v0.w
             + v1.x*v1.x + v1.y*v1.y + v1.z*v1.z + v1.w*v1.w;
    #pragma unroll
    for (int o = 16; o > 0; o >>= 1) {
        s  += __shfl_xor_sync(0xFFFFFFFFu, s,  o);
        ss += __shfl_xor_sync(0xFFFFFFFFu, ss, o);
    }
    __shared__ float sh_s[8], sh_ss[8];
    if ((tid & 31) == 0) { sh_s[tid >> 5] = s; sh_ss[tid >> 5] = ss; }
    __syncthreads();
    float ts = 0.f, tss = 0.f;
    #pragma unroll
    for (int i = 0; i < 8; i++) { ts += sh_s[i]; tss += sh_ss[i]; }
    const float mean = ts * (1.0f / D);
    const float inv  = rsqrtf(tss * (1.0f / D) - mean * mean + 1e-5f);

    const float4* g4 = reinterpret_cast<const float4*>(g);
    const float4* b4 = reinterpret_cast<const float4*>(b);
    __half2* o2 = reinterpret_cast<__half2*>(out + (size_t)row * D);
    float4 ga0 = g4[tid],       gb0 = b4[tid];
    float4 ga1 = g4[tid + 256], gb1 = b4[tid + 256];
    o2[tid * 2]     = __floats2half2_rn((v0.x - mean) * inv * ga0.x + gb0.x,
                                        (v0.y - mean) * inv * ga0.y + gb0.y);
    o2[tid * 2 + 1] = __floats2half2_rn((v0.z - mean) * inv * ga0.z + gb0.z,
                                        (v0.w - mean) * inv * ga0.w + gb0.w);
    o2[(tid + 256) * 2]     = __floats2half2_rn((v1.x - mean) * inv * ga1.x + gb1.x,
                                                (v1.y - mean) * inv * ga1.y + gb1.y);
    o2[(tid + 256) * 2 + 1] = __floats2half2_rn((v1.z - mean) * inv * ga1.z + gb1.z,
                                                (v1.w - mean) * inv * ga1.w + gb1.w);
}

__global__ void __launch_bounds__(256) ln2048_f16in(
    const __half* __restrict__ x, const float* __restrict__ g,
    const float* __restrict__ b, __half* __restrict__ out)
{
    constexpr int D = 2048;
    const int row = blockIdx.x;
    const int tid = threadIdx.x;
    const uint2* xr = reinterpret_cast<const uint2*>(x + (size_t)row * D);
    uint2 u0 = xr[tid];
    uint2 u1 = xr[tid + 256];
    float2 a0 = __half22float2(*reinterpret_cast<__half2*>(&u0.x));
    float2 a1 = __half22float2(*reinterpret_cast<__half2*>(&u0.y));
    float2 a2 = __half22float2(*reinterpret_cast<__half2*>(&u1.x));
    float2 a3 = __half22float2(*reinterpret_cast<__half2*>(&u1.y));

    float s  = a0.x + a0.y + a1.x + a1.y + a2.x + a2.y + a3.x + a3.y;
    float ss = a0.x*a0.x + a0.y*a0.y + a1.x*a1.x + a1.y*a1.y
             + a2.x*a2.x + a2.y*a2.y + a3.x*a3.x + a3.y*a3.y;
    #pragma unroll
    for (int o = 16; o > 0; o >>= 1) {
        s  += __shfl_xor_sync(0xFFFFFFFFu, s,  o);
        ss += __shfl_xor_sync(0xFFFFFFFFu, ss, o);
    }
    __shared__ float sh_s[8], sh_ss[8];
    if ((tid & 31) == 0) { sh_s[tid >> 5] = s; sh_ss[tid >> 5] = ss; }
    __syncthreads();
    float ts = 0.f, tss = 0.f;
    #pragma unroll
    for (int i = 0; i < 8; i++) { ts += sh_s[i]; tss += sh_ss[i]; }
    const float mean = ts * (1.0f / D);
    const float inv  = rsqrtf(tss * (1.0f / D) - mean * mean + 1e-5f);

    const float4* g4 = reinterpret_cast<const float4*>(g);
    const float4* b4 = reinterpret_cast<const float4*>(b);
    __half2* o2 = reinterpret_cast<__half2*>(out + (size_t)row * D);
    float4 ga0 = g4[tid],       gb0 = b4[tid];
    float4 ga1 = g4[tid + 256], gb1 = b4[tid + 256];
    o2[tid * 2]     = __floats2half2_rn((a0.x - mean) * inv * ga0.x + gb0.x,
                                        (a0.y - mean) * inv * ga0.y + gb0.y);
    o2[tid * 2 + 1] = __floats2half2_rn((a1.x - mean) * inv * ga0.z + gb0.z,
                                        (a1.y - mean) * inv * ga0.w + gb0.w);
    o2[(tid + 256) * 2]     = __floats2half2_rn((a2.x - mean) * inv * ga1.x + gb1.x,
                                                (a2.y - mean) * inv * ga1.y + gb1.y);
    o2[(tid + 256) * 2 + 1] = __floats2half2_rn((a3.x - mean) * inv * ga1.z + gb1.z,
                                                (a3.y - mean) * inv * ga1.w + gb1.w);
}

// ---------------------------------------------------------------------------
extern "C" void kernel_launch(void* const* d_in, const int* in_sizes, int n_in,
                              void* d_out, int out_size)
{
    const float* x_t    = (const float*)d_in[0];
    const float* h_prev = (const float*)d_in[1];
    const float* W_proj = (const float*)d_in[2];
    const float* b_proj = (const float*)d_in[3];
    const float* in_w   = (const float*)d_in[4];
    const float* in_b   = (const float*)d_in[5];
    const float* out_w  = (const float*)d_in[6];
    const float* out_b  = (const float*)d_in[7];
    const float* ln1_g  = (const float*)d_in[8];
    const float* ln1_b  = (const float*)d_in[9];
    const float* ln2_g  = (const float*)d_in[10];
    const float* ln2_b  = (const float*)d_in[11];
    const float* gate_a = (const float*)d_in[12];
    const float* gate_b = (const float*)d_in[13];
    const float* ffn_w1 = (const float*)d_in[14];
    const float* ffn_b1 = (const float*)d_in[15];
    const float* ffn_w2 = (const float*)d_in[16];
    const float* ffn_b2 = (const float*)d_in[17];
    float* out = (float*)d_out;

    float *phh, *pbvo, *pzb;
    __half *px16, *pxh, *pqn16, *py16, *pt16;
    __half *pwp, *pwvT, *pwo, *pwvo, *pw1, *pw2;
    cudaGetSymbolAddress((void**)&phh,   g_hhat);
    cudaGetSymbolAddress((void**)&pbvo,  g_bvo);
    cudaGetSymbolAddress((void**)&pzb,   g_zb);
    cudaGetSymbolAddress((void**)&px16,  g_x16);
    cudaGetSymbolAddress((void**)&pxh,   g_xh);
    cudaGetSymbolAddress((void**)&pqn16, g_qn16);
    cudaGetSymbolAddress((void**)&py16,  g_y16);
    cudaGetSymbolAddress((void**)&pt16,  g_t16);
    cudaGetSymbolAddress((void**)&pwp,   g_wp16);
    cudaGetSymbolAddress((void**)&pwvT,  g_wvT16);
    cudaGetSymbolAddress((void**)&pwo,   g_wo16);
    cudaGetSymbolAddress((void**)&pwvo,  g_wvo16);
    cudaGetSymbolAddress((void**)&pw1,   g_w1_16);
    cudaGetSymbolAddress((void**)&pw2,   g_w2_16);

    cudaFuncSetAttribute(gemm16<2,0,1>, cudaFuncAttributeMaxDynamicSharedMemorySize, GSMEM);
    cudaFuncSetAttribute(gemm16<3,1,0>, cudaFuncAttributeMaxDynamicSharedMemorySize, GSMEM);
    cudaFuncSetAttribute(gemmDual,      cudaFuncAttributeMaxDynamicSharedMemorySize, GSMEM);
    cudaFuncSetAttribute(gemmGateCvt,   cudaFuncAttributeMaxDynamicSharedMemorySize, GSMEM);

    // launch 0: prep = cvt(wp, wo, x) + WvT transpose + bvo
    prep<<<PREP_BLKS, 256>>>(
        W_proj, pwp, D_MODEL * 1024,
        out_w, pwo, D_MODEL * D_MODEL,
        x_t, px16, B_DIM * 1024,
        in_w + (size_t)2 * D_MODEL * D_MODEL, pwvT,
        out_w, in_b + 2 * D_MODEL, out_b, pbvo);

    const dim3 blk(256);
    const dim3 gF (D_FF / BN, B_DIM / BM);   // 64 x 32
    const dim3 gD (D_MODEL / BN, B_DIM / BM);

    // launch 1: gemmDual = Wvo + G1 (pure GEMM)
    gemmDual<<<DUAL_BLKS, blk, GSMEM>>>(
        pwo, pwvT, pzb, pwvo,
        px16, pwp, b_proj, pxh);
    // launch 2: L1
    ln2048_f16in<<<B_DIM, 256>>>(pxh, ln1_g, ln1_b, pqn16);
    // launch 3: gemmGateCvt = G23 + w1/w2 cvt  <-- global ncu index 5
    gemmGateCvt<<<GATE_BLKS, blk, GSMEM>>>(
        pqn16, pwvo, pbvo, phh,
        h_prev, gate_a, gate_b,
        ffn_w1, pw1, D_FF * D_MODEL,
        ffn_w2, pw2);
    // launch 4: L2
    ln2048_f32in<<<B_DIM, 256>>>(phh, ln2_g, ln2_b, py16);
    // launch 5: G4
    gemm16<2,0,1><<<gF, blk, GSMEM>>>(py16, pw1, ffn_b1, nullptr, pt16, nullptr,
                                      nullptr, nullptr, nullptr, D_FF, D_MODEL);
    // launch 6: G5 (dual fp32 store)
    float* out2 = (out_size >= 2 * B_DIM * D_MODEL) ? (out + (size_t)B_DIM * D_MODEL) : out;
    gemm16<3,1,0><<<gD, blk, GSMEM>>>(pt16, pw2, ffn_b2, out, nullptr, out2,
                                      phh, nullptr, nullptr, D_MODEL, D_FF);
}

// round 14
// speedup vs baseline: 1.0680x; 1.0149x over previous
#include <cuda_runtime.h>
#include <cuda_fp16.h>
#include <cstdint>
#include <cstddef>

// ---------------------------------------------------------------------------
// GTrXLCell round 14: schedule packing at the mma.sync roofline.
//  - w1/w2 cvt split across gemmDualCvt / gemmGateCvt tails (half each).
//  - gemmFFN: G4 (2048 blks) + G5 (512 blks) fused in ONE launch with
//    per-row-block atomic readiness counters (G5 overlaps G4's tail wave).
//  - prep zeroes the counters every call (graph-replay safe).
// Champion GEMM mainloop byte-frozen since round 8.
// ---------------------------------------------------------------------------

#define B_DIM     4096
#define D_MODEL   2048
#define D_FF      8192

__device__ float  g_hhat[(size_t)B_DIM * D_MODEL];
__device__ __half g_x16 [(size_t)B_DIM * 1024];
__device__ __half g_xh  [(size_t)B_DIM * D_MODEL];
__device__ __half g_qn16[(size_t)B_DIM * D_MODEL];
__device__ __half g_y16 [(size_t)B_DIM * D_MODEL];
__device__ __half g_t16 [(size_t)B_DIM * D_FF];
__device__ __half g_wp16 [(size_t)D_MODEL * 1024];
__device__ __half g_wvT16[(size_t)D_MODEL * D_MODEL];
__device__ __half g_wo16 [(size_t)D_MODEL * D_MODEL];
__device__ __half g_wvo16[(size_t)D_MODEL * D_MODEL];
__device__ float  g_bvo  [D_MODEL];
__device__ float  g_zb   [D_MODEL];
__device__ __half g_w1_16[(size_t)D_FF * D_MODEL];
__device__ __half g_w2_16[(size_t)D_MODEL * D_FF];
__device__ int    g_cnt  [B_DIM / 128];            // 32 row-block counters

// ------------------------------ helpers -----------------------------------
__device__ __forceinline__ uint32_t smem_u32(const void* p) {
    uint32_t a;
    asm("{ .reg .u64 t; cvta.to.shared.u64 t, %1; cvt.u32.u64 %0, t; }"
        : "=r"(a) : "l"(p));
    return a;
}
__device__ __forceinline__ void cp16(uint32_t dst, const void* src) {
    asm volatile("cp.async.cg.shared.global [%0], [%1], 16;"
                 :: "r"(dst), "l"(src));
}
#define CP_COMMIT() asm volatile("cp.async.commit_group;" ::: "memory")
#define CP_WAIT1()  asm volatile("cp.async.wait_group 1;" ::: "memory")
#define CP_WAIT0()  asm volatile("cp.async.wait_group 0;" ::: "memory")

__device__ __forceinline__ void ldsm_x4(uint32_t& r0, uint32_t& r1,
                                        uint32_t& r2, uint32_t& r3, uint32_t addr) {
    asm volatile("ldmatrix.sync.aligned.m8n8.x4.shared.b16 {%0,%1,%2,%3}, [%4];"
                 : "=r"(r0), "=r"(r1), "=r"(r2), "=r"(r3) : "r"(addr));
}
__device__ __forceinline__ void mma_f16(float c[4], const uint32_t a[4],
                                        const uint32_t b[2]) {
    asm volatile(
        "mma.sync.aligned.m16n8k16.row.col.f32.f16.f16.f32 "
        "{%0,%1,%2,%3}, {%4,%5,%6,%7}, {%8,%9}, {%0,%1,%2,%3};\n"
        : "+f"(c[0]), "+f"(c[1]), "+f"(c[2]), "+f"(c[3])
        : "r"(a[0]), "r"(a[1]), "r"(a[2]), "r"(a[3]), "r"(b[0]), "r"(b[1]));
}
__device__ __forceinline__ float sigmoidf_(float x) { return 1.0f / (1.0f + expf(-x)); }
__device__ __forceinline__ float gelu_exact(float x) {
    return 0.5f * x * (1.0f + erff(x * 0.70710678118654752f));
}
__device__ __forceinline__ void cvt4d(const float* s, __half* d, int i) {
    float4 v = *reinterpret_cast<const float4*>(s + i);
    *reinterpret_cast<__half2*>(d + i)     = __floats2half2_rn(v.x, v.y);
    *reinterpret_cast<__half2*>(d + i + 2) = __floats2half2_rn(v.z, v.w);
}

// ---------------------------------------------------------------------------
// Champion GEMM constants + mainloop macro (frozen since round 8)
// ---------------------------------------------------------------------------
constexpr int BM = 128, BN = 128, BKH = 64;
constexpr int LDT = 72;
constexpr int TILE_A = BM * LDT;
constexpr uint32_t STAGE_BYTES = 2u * (uint32_t)TILE_A * 2u;   // 36864 B
constexpr int STAGES = 3;
constexpr uint32_t GSMEM = STAGES * STAGE_BYTES;               // 110592 B

#define GEMM_MAINLOOP(A_, B_, K_, block_row_, block_col_)                      \
    const int tid  = threadIdx.x;                                             \
    const int warp = tid >> 5;                                                 \
    const int lane = tid & 31;                                                 \
    const int wm = warp >> 2;                                                  \
    const int wn = warp & 3;                                                   \
    const int gr = lane >> 2;                                                  \
    const int tg = lane & 3;                                                   \
    const int KT = (K_) / BKH;                                                 \
    const int r0   = tid >> 3;                                                 \
    const int scol = (tid & 7) * 8;                                            \
    const __half* Agp[4];                                                      \
    const __half* Bgp[4];                                                      \
    uint32_t dA[4], dB[4];                                                     \
    _Pragma("unroll")                                                          \
    for (int k = 0; k < 4; k++) {                                              \
        const int rw = r0 + 32 * k;                                            \
        Agp[k] = (A_) + (size_t)((block_row_) + rw) * (K_) + scol;             \
        Bgp[k] = (B_) + (size_t)((block_col_) + rw) * (K_) + scol;             \
        dA[k] = (uint32_t)(rw * LDT + scol) * 2u;                              \
        dB[k] = (uint32_t)(TILE_A + rw * LDT + scol) * 2u;                     \
    }                                                                          \
    const int j = lane >> 3, r = lane & 7;                                     \
    uint32_t aoff[4], boff[2];                                                 \
    _Pragma("unroll")                                                          \
    for (int mi = 0; mi < 4; mi++)                                             \
        aoff[mi] = (uint32_t)(((wm * 64 + mi * 16 + (j & 1) * 8 + r) * LDT     \
                               + (j >> 1) * 8) * 2);                           \
    _Pragma("unroll")                                                          \
    for (int n2 = 0; n2 < 2; n2++)                                             \
        boff[n2] = (uint32_t)((TILE_A                                          \
                               + (wn * 32 + n2 * 16 + (j >> 1) * 8 + r) * LDT  \
                               + (j & 1) * 8) * 2);                            \
    float acc[4][4][4];                                                        \
    _Pragma("unroll")                                                          \
    for (int mi = 0; mi < 4; mi++)                                             \
        _Pragma("unroll")                                                      \
        for (int ni = 0; ni < 4; ni++)                                         \
            _Pragma("unroll")                                                  \
            for (int q = 0; q < 4; q++) acc[mi][ni][q] = 0.0f;                 \
    auto stage_fill = [&](int kt, int st) {                                    \
        const uint32_t sb = sbase + (uint32_t)st * STAGE_BYTES;                \
        const size_t ko = (size_t)kt * BKH;                                    \
        _Pragma("unroll")                                                      \
        for (int k = 0; k < 4; k++) cp16(sb + dA[k], Agp[k] + ko);             \
        _Pragma("unroll")                                                      \
        for (int k = 0; k < 4; k++) cp16(sb + dB[k], Bgp[k] + ko);             \
        CP_COMMIT();                                                           \
    };                                                                         \
    stage_fill(0, 0);                                                          \
    if (KT > 1) stage_fill(1, 1);                                              \
    for (int kt = 0; kt < KT; kt++) {                                          \
        if (kt + 1 < KT) CP_WAIT1(); else CP_WAIT0();                          \
        __syncthreads();                                                       \
        if (kt + 2 < KT) {                                                     \
            int st = (kt + 2) % STAGES;                                        \
            stage_fill(kt + 2, st);                                            \
        }                                                                      \
        const uint32_t sb = sbase + (uint32_t)(kt % STAGES) * STAGE_BYTES;     \
        _Pragma("unroll")                                                      \
        for (int ks = 0; ks < 4; ks++) {                                       \
            const uint32_t kk = ks * 32;                                       \
            uint32_t af[4][4];                                                 \
            _Pragma("unroll")                                                  \
            for (int mi = 0; mi < 4; mi++)                                     \
                ldsm_x4(af[mi][0], af[mi][1], af[mi][2], af[mi][3],            \
                        sb + aoff[mi] + kk);                                   \
            uint32_t bf[4][2];                                                 \
            _Pragma("unroll")                                                  \
            for (int n2 = 0; n2 < 2; n2++) {                                   \
                uint32_t b0, b1, b2, b3;                                       \
                ldsm_x4(b0, b1, b2, b3, sb + boff[n2] + kk);                   \
                bf[n2 * 2][0] = b0; bf[n2 * 2][1] = b1;                        \
                bf[n2 * 2 + 1][0] = b2; bf[n2 * 2 + 1][1] = b3;                \
            }                                                                  \
            _Pragma("unroll")                                                  \
            for (int mi = 0; mi < 4; mi++)                                     \
                _Pragma("unroll")                                              \
                for (int ni = 0; ni < 4; ni++)                                 \
                    mma_f16(acc[mi][ni], af[mi], bf[ni]);                      \
        }                                                                      \
    }

constexpr int CVT_ELEMS_PER_BLK = 8192;

// ---------------------------------------------------------------------------
// gemmDualCvt: Wvo (256) + G1 (512) + w1 cvt (2048 trailing blocks)
// ---------------------------------------------------------------------------
constexpr int DUAL_WVO_TILES = (D_MODEL / BN) * (D_MODEL / BM);   // 256
constexpr int DUAL_G1_TILES  = (D_MODEL / BN) * (B_DIM / BM);     // 512
constexpr int DUAL_GEMM_BLKS = DUAL_WVO_TILES + DUAL_G1_TILES;    // 768
constexpr int DUAL_CVT_BLKS  = (D_FF * D_MODEL) / CVT_ELEMS_PER_BLK;  // 2048
constexpr int DUAL_BLKS      = DUAL_GEMM_BLKS + DUAL_CVT_BLKS;

__global__ void __launch_bounds__(256, 2) gemmDualCvt(
    const __half* __restrict__ Aw,  const __half* __restrict__ Bww,
    const float* __restrict__ biasw, __half* __restrict__ Cw,
    const __half* __restrict__ Ag,  const __half* __restrict__ Bwg,
    const float* __restrict__ biasg, __half* __restrict__ Cg,
    const float* __restrict__ s1, __half* __restrict__ d1)
{
    const int bid = blockIdx.x;

    if (bid >= DUAL_GEMM_BLKS) {                 // w1 cvt
        const int cb = bid - DUAL_GEMM_BLKS;
        const int t  = threadIdx.x;
        const int base = cb * CVT_ELEMS_PER_BLK;
        #pragma unroll
        for (int jj = 0; jj < 8; jj++)
            cvt4d(s1, d1, base + (jj * 256 + t) * 4);
        return;
    }

    const __half* A;  const __half* Bw;  const float* bias;  __half* C16;
    int bx, by, K;
    if (bid < DUAL_WVO_TILES) {
        A = Aw; Bw = Bww; bias = biasw; C16 = Cw; K = D_MODEL;
        bx = bid & 15; by = bid >> 4;
    } else {
        const int g = bid - DUAL_WVO_TILES;
        A = Ag; Bw = Bwg; bias = biasg; C16 = Cg; K = 1024;
        bx = g & 15; by = g >> 4;
    }
    const int N = D_MODEL;

    extern __shared__ char smraw[];
    const uint32_t sbase = smem_u32(smraw);
    const int block_row = by * BM;
    const int block_col = bx * BN;

    GEMM_MAINLOOP(A, Bw, K, block_row, block_col)

    #pragma unroll
    for (int mi = 0; mi < 4; mi++) {
        #pragma unroll
        for (int ni = 0; ni < 4; ni++) {
            const int col = block_col + wn * 32 + ni * 8 + 2 * tg;
            const float b0 = bias[col], b1 = bias[col + 1];
            #pragma unroll
            for (int h = 0; h < 2; h++) {
                const int row = block_row + wm * 64 + mi * 16 + gr + h * 8;
                const size_t off = (size_t)row * N + col;
                *reinterpret_cast<__half2*>(&C16[off]) =
                    __floats2half2_rn(acc[mi][ni][2 * h + 0] + b0,
                                      acc[mi][ni][2 * h + 1] + b1);
            }
        }
    }
}

// ---------------------------------------------------------------------------
// gemmGateCvt: G23 (512) + w2 cvt (2048 trailing blocks)
// ---------------------------------------------------------------------------
constexpr int GATE_GEMM_BLKS = (D_MODEL / BN) * (B_DIM / BM);     // 512
constexpr int GATE_CVT_BLKS  = (D_MODEL * D_FF) / CVT_ELEMS_PER_BLK;  // 2048
constexpr int GATE_BLKS      = GATE_GEMM_BLKS + GATE_CVT_BLKS;

__global__ void __launch_bounds__(256, 2) gemmGateCvt(
    const __half* __restrict__ A, const __half* __restrict__ Bw,
    const float* __restrict__ bias, float* __restrict__ C32,
    const float* __restrict__ aux,
    const float* __restrict__ ga, const float* __restrict__ gb,
    const float* __restrict__ s2, __half* __restrict__ d2)
{
    const int bid = blockIdx.x;

    if (bid >= GATE_GEMM_BLKS) {                 // w2 cvt
        const int cb = bid - GATE_GEMM_BLKS;
        const int t  = threadIdx.x;
        const int base = cb * CVT_ELEMS_PER_BLK;
        #pragma unroll
        for (int jj = 0; jj < 8; jj++)
            cvt4d(s2, d2, base + (jj * 256 + t) * 4);
        return;
    }

    const int bx = bid & 15, by = bid >> 4;
    const int N = D_MODEL, K = D_MODEL;

    extern __shared__ char smraw[];
    const uint32_t sbase = smem_u32(smraw);
    const int block_row = by * BM;
    const int block_col = bx * BN;

    GEMM_MAINLOOP(A, Bw, K, block_row, block_col)

    #pragma unroll
    for (int mi = 0; mi < 4; mi++) {
        #pragma unroll
        for (int ni = 0; ni < 4; ni++) {
            const int col = block_col + wn * 32 + ni * 8 + 2 * tg;
            const float b0 = bias[col], b1 = bias[col + 1];
            const float sa0 = sigmoidf_(ga[col]),     sa1 = sigmoidf_(ga[col + 1]);
            const float sb0 = sigmoidf_(gb[col]),     sb1 = sigmoidf_(gb[col + 1]);
            #pragma unroll
            for (int h = 0; h < 2; h++) {
                const int row = block_row + wm * 64 + mi * 16 + gr + h * 8;
                const size_t off = (size_t)row * N + col;
                float v0 = sa0 * aux[off]     + sb0 * (acc[mi][ni][2 * h + 0] + b0);
                float v1 = sa1 * aux[off + 1] + sb1 * (acc[mi][ni][2 * h + 1] + b1);
                *reinterpret_cast<float2*>(&C32[off]) = make_float2(v0, v1);
            }
        }
    }
}

// ---------------------------------------------------------------------------
// gemmFFN: G4 (2048 blocks, row-major) + G5 (512 blocks) fused with per-
// row-block readiness counters. G5 block (by) waits for the 64 G4 blocks
// of the same row-block, then computes out = hhat + t16 @ w2^T + b2.
// ---------------------------------------------------------------------------
constexpr int FFN_G4_BLKS = (D_FF / BN) * (B_DIM / BM);       // 2048
constexpr int FFN_G5_BLKS = (D_MODEL / BN) * (B_DIM / BM);    // 512
constexpr int FFN_BLKS    = FFN_G4_BLKS + FFN_G5_BLKS;

__global__ void __launch_bounds__(256, 2) gemmFFN(
    const __half* __restrict__ y16, const __half* __restrict__ w1,
    const float* __restrict__ b1,   __half* __restrict__ t16,
    const __half* __restrict__ w2,  const float* __restrict__ b2,
    const float* __restrict__ aux,
    float* __restrict__ out, float* __restrict__ out2)
{
    const int bid = blockIdx.x;
    extern __shared__ char smraw[];
    const uint32_t sbase = smem_u32(smraw);

    if (bid < FFN_G4_BLKS) {
        // ---- G4: t16 = gelu(y16 @ w1^T + b1), row-major block order ----
        const int by = bid >> 6, bx = bid & 63;
        const int N = D_FF, K = D_MODEL;
        const int block_row = by * BM;
        const int block_col = bx * BN;

        GEMM_MAINLOOP(y16, w1, K, block_row, block_col)

        #pragma unroll
        for (int mi = 0; mi < 4; mi++) {
            #pragma unroll
            for (int ni = 0; ni < 4; ni++) {
                const int col = block_col + wn * 32 + ni * 8 + 2 * tg;
                const float bb0 = b1[col], bb1 = b1[col + 1];
                #pragma unroll
                for (int h = 0; h < 2; h++) {
                    const int row = block_row + wm * 64 + mi * 16 + gr + h * 8;
                    const size_t off = (size_t)row * N + col;
                    *reinterpret_cast<__half2*>(&t16[off]) =
                        __floats2half2_rn(gelu_exact(acc[mi][ni][2 * h + 0] + bb0),
                                          gelu_exact(acc[mi][ni][2 * h + 1] + bb1));
                }
            }
        }
        __threadfence();
        __syncthreads();
        if (tid == 0) atomicAdd(&g_cnt[by], 1);
    } else {
        // ---- G5: out = aux + t16 @ w2^T + b2 (dual fp32 store) ----
        const int g = bid - FFN_G4_BLKS;
        const int by = g >> 4, bx = g & 15;

        if (threadIdx.x == 0) {
            while (atomicAdd(&g_cnt[by], 0) < 64) { }
        }
        __syncthreads();

        const int N = D_MODEL, K = D_FF;
        const int block_row = by * BM;
        const int block_col = bx * BN;

        GEMM_MAINLOOP(t16, w2, K, block_row, block_col)

        #pragma unroll
        for (int mi = 0; mi < 4; mi++) {
            #pragma unroll
            for (int ni = 0; ni < 4; ni++) {
                const int col = block_col + wn * 32 + ni * 8 + 2 * tg;
                const float bb0 = b2[col], bb1 = b2[col + 1];
                #pragma unroll
                for (int h = 0; h < 2; h++) {
                    const int row = block_row + wm * 64 + mi * 16 + gr + h * 8;
                    const size_t off = (size_t)row * N + col;
                    const float v0 = acc[mi][ni][2 * h + 0] + bb0 + aux[off];
                    const float v1 = acc[mi][ni][2 * h + 1] + bb1 + aux[off + 1];
                    float2 o = make_float2(v0, v1);
                    *reinterpret_cast<float2*>(&out[off])  = o;
                    *reinterpret_cast<float2*>(&out2[off]) = o;
                }
            }
        }
    }
}

// ---------------------------------------------------------------------------
// prep: cvt(wp, wo, x_t) + WvT transpose + bvo bias prep + counter zero.
// ---------------------------------------------------------------------------
constexpr int PREP_CVT_ELEMS = D_MODEL * 1024 + D_MODEL * D_MODEL + B_DIM * 1024;
constexpr int PREP_CVT_BLKS  = PREP_CVT_ELEMS / CVT_ELEMS_PER_BLK;       // 1280
constexpr int PREP_TRAN_BLKS = (D_MODEL / 32) * (D_MODEL / 32);          // 4096
constexpr int PREP_BIAS_BLKS = D_MODEL / 8;                              // 256
constexpr int PREP_BLKS = PREP_CVT_BLKS + PREP_TRAN_BLKS + PREP_BIAS_BLKS;

__global__ void __launch_bounds__(256) prep(
    const float* s0, __half* d0, int n0,
    const float* s1, __half* d1, int n1,
    const float* s2, __half* d2, int n2,
    const float* __restrict__ wvsrc, __half* __restrict__ wvTdst,
    const float* __restrict__ out_w, const float* __restrict__ bv,
    const float* __restrict__ out_b, float* __restrict__ bvo)
{
    const int bid = blockIdx.x;
    const int tid = threadIdx.x;

    if (bid < PREP_CVT_BLKS) {
        const int base = bid * CVT_ELEMS_PER_BLK;
        #pragma unroll
        for (int jj = 0; jj < 8; jj++) {
            int i = base + (jj * 256 + tid) * 4;
            if (i < n0)                { cvt4d(s0, d0, i); continue; }
            i -= n0;
            if (i < n1)                { cvt4d(s1, d1, i); continue; }
            i -= n1;
            if (i < n2)                { cvt4d(s2, d2, i); }
        }
        return;
    }

    if (bid < PREP_CVT_BLKS + PREP_TRAN_BLKS) {
        __shared__ float tile[32][33];
        const int b2 = bid - PREP_CVT_BLKS;
        const int bx = b2 & 63, by = b2 >> 6;
        const int tx = tid & 31, ty = tid >> 5;
        const int x = bx * 32 + tx;
        const int y = by * 32 + ty;
        #pragma unroll
        for (int jj = 0; jj < 32; jj += 8)
            tile[ty + jj][tx] = wvsrc[(size_t)(y + jj) * D_MODEL + x];
        __syncthreads();
        const int x2 = by * 32 + tx;
        const int y2 = bx * 32 + ty;
        #pragma unroll
        for (int jj = 0; jj < 32; jj += 8)
            wvTdst[(size_t)(y2 + jj) * D_MODEL + x2] =
                __float2half_rn(tile[tx][ty + jj]);
        return;
    }

    const int b3 = bid - PREP_CVT_BLKS - PREP_TRAN_BLKS;
    if (b3 == 0 && tid < 32) g_cnt[tid] = 0;      // zero counters (graph-safe)
    const int warp = tid >> 5, lane = tid & 31;
    const int m = b3 * 8 + warp;
    const float* row = out_w + (size_t)m * D_MODEL;
    float s = 0.f;
    for (int k = lane; k < D_MODEL; k += 32) s += row[k] * bv[k];
    #pragma unroll
    for (int o = 16; o > 0; o >>= 1) s += __shfl_xor_sync(0xFFFFFFFFu, s, o);
    if (lane == 0) bvo[m] = s + out_b[m];
}

// ---------------------------------------------------------------------------
// LayerNorm D=2048
// ---------------------------------------------------------------------------
__global__ void __launch_bounds__(256) ln2048_f32in(
    const float* __restrict__ x, const float* __restrict__ g,
    const float* __restrict__ b, __half* __restrict__ out)
{
    constexpr int D = 2048;
    const int row = blockIdx.x;
    const int tid = threadIdx.x;
    const float4* xr = reinterpret_cast<const float4*>(x + (size_t)row * D);

    float4 v0 = xr[tid];
    float4 v1 = xr[tid + 256];
    float s  = v0.x + v0.y + v0.z + v0.w + v1.x + v1.y + v1.z + v1.w;
    float ss = v0.x*v0.x + v0.y*v0.y + v0.z*v0.z + v0.w*v0.w
             + v1.x*v1.x + v1.y*v1.y + v1.z*v1.z + v1.w*v1.w;
    #pragma unroll
    for (int o = 16; o > 0; o >>= 1) {
        s  += __shfl_xor_sync(0xFFFFFFFFu, s,  o);
        ss += __shfl_xor_sync(0xFFFFFFFFu, ss, o);
    }
    __shared__ float sh_s[8], sh_ss[8];
    if ((tid & 31) == 0) { sh_s[tid >> 5] = s; sh_ss[tid >> 5] = ss; }
    __syncthreads();
    float ts = 0.f, tss = 0.f;
    #pragma unroll
    for (int i = 0; i < 8; i++) { ts += sh_s[i]; tss += sh_ss[i]; }
    const float mean = ts * (1.0f / D);
    const float inv  = rsqrtf(tss * (1.0f / D) - mean * mean + 1e-5f);

    const float4* g4 = reinterpret_cast<const float4*>(g);
    const float4* b4 = reinterpret_cast<const float4*>(b);
    __half2* o2 = reinterpret_cast<__half2*>(out + (size_t)row * D);
    float4 ga0 = g4[tid],       gb0 = b4[tid];
    float4 ga1 = g4[tid + 256], gb1 = b4[tid + 256];
    o2[tid * 2]     = __floats2half2_rn((v0.x - mean) * inv * ga0.x + gb0.x,
                                        (v0.y - mean) * inv * ga0.y + gb0.y);
    o2[tid * 2 + 1] = __floats2half2_rn((v0.z - mean) * inv * ga0.z + gb0.z,
                                        (v0.w - mean) * inv * ga0.w + gb0.w);
    o2[(tid + 256) * 2]     = __floats2half2_rn((v1.x - mean) * inv * ga1.x + gb1.x,
                                                (v1.y - mean) * inv * ga1.y + gb1.y);
    o2[(tid + 256) * 2 + 1] = __floats2half2_rn((v1.z - mean) * inv * ga1.z + gb1.z,
                                                (v1.w - mean) * inv * ga1.w + gb1.w);
}

__global__ void __launch_bounds__(256) ln2048_f16in(
    const __half* __restrict__ x, const float* __restrict__ g,
    const float* __restrict__ b, __half* __restrict__ out)
{
    constexpr int D = 2048;
    const int row = blockIdx.x;
    const int tid = threadIdx.x;
    const uint2* xr = reinterpret_cast<const uint2*>(x + (size_t)row * D);
    uint2 u0 = xr[tid];
    uint2 u1 = xr[tid + 256];
    float2 a0 = __half22float2(*reinterpret_cast<__half2*>(&u0.x));
    float2 a1 = __half22float2(*reinterpret_cast<__half2*>(&u0.y));
    float2 a2 = __half22float2(*reinterpret_cast<__half2*>(&u1.x));
    float2 a3 = __half22float2(*reinterpret_cast<__half2*>(&u1.y));

    float s  = a0.x + a0.y + a1.x + a1.y + a2.x + a2.y + a3.x + a3.y;
    float ss = a0.x*a0.x + a0.y*a0.y + a1.x*a1.x + a1.y*a1.y
             + a2.x*a2.x + a2.y*a2.y + a3.x*a3.x + a3.y*a3.y;
    #pragma unroll
    for (int o = 16; o > 0; o >>= 1) {
        s  += __shfl_xor_sync(0xFFFFFFFFu, s,  o);
        ss += __shfl_xor_sync(0xFFFFFFFFu, ss, o);
    }
    __shared__ float sh_s[8], sh_ss[8];
    if ((tid & 31) == 0) { sh_s[tid >> 5] = s; sh_ss[tid >> 5] = ss; }
    __syncthreads();
    float ts = 0.f, tss = 0.f;
    #pragma unroll
    for (int i = 0; i < 8; i++) { ts += sh_s[i]; tss += sh_ss[i]; }
    const float mean = ts * (1.0f / D);
    const float inv  = rsqrtf(tss * (1.0f / D) - mean * mean + 1e-5f);

    const float4* g4 = reinterpret_cast<const float4*>(g);
    const float4* b4 = reinterpret_cast<const float4*>(b);
    __half2* o2 = reinterpret_cast<__half2*>(out + (size_t)row * D);
    float4 ga0 = g4[tid],       gb0 = b4[tid];
    float4 ga1 = g4[tid + 256], gb1 = b4[tid + 256];
    o2[tid * 2]     = __floats2half2_rn((a0.x - mean) * inv * ga0.x + gb0.x,
                                        (a0.y - mean) * inv * ga0.y + gb0.y);
    o2[tid * 2 + 1] = __floats2half2_rn((a1.x - mean) * inv * ga0.z + gb0.z,
                                        (a1.y - mean) * inv * ga0.w + gb0.w);
    o2[(tid + 256) * 2]     = __floats2half2_rn((a2.x - mean) * inv * ga1.x + gb1.x,
                                                (a2.y - mean) * inv * ga1.y + gb1.y);
    o2[(tid + 256) * 2 + 1] = __floats2half2_rn((a3.x - mean) * inv * ga1.z + gb1.z,
                                                (a3.y - mean) * inv * ga1.w + gb1.w);
}

// ---------------------------------------------------------------------------
extern "C" void kernel_launch(void* const* d_in, const int* in_sizes, int n_in,
                              void* d_out, int out_size)
{
    const float* x_t    = (const float*)d_in[0];
    const float* h_prev = (const float*)d_in[1];
    const float* W_proj = (const float*)d_in[2];
    const float* b_proj = (const float*)d_in[3];
    const float* in_w   = (const float*)d_in[4];
    const float* in_b   = (const float*)d_in[5];
    const float* out_w  = (const float*)d_in[6];
    const float* out_b  = (const float*)d_in[7];
    const float* ln1_g  = (const float*)d_in[8];
    const float* ln1_b  = (const float*)d_in[9];
    const float* ln2_g  = (const float*)d_in[10];
    const float* ln2_b  = (const float*)d_in[11];
    const float* gate_a = (const float*)d_in[12];
    const float* gate_b = (const float*)d_in[13];
    const float* ffn_w1 = (const float*)d_in[14];
    const float* ffn_b1 = (const float*)d_in[15];
    const float* ffn_w2 = (const float*)d_in[16];
    const float* ffn_b2 = (const float*)d_in[17];
    float* out = (float*)d_out;

    float *phh, *pbvo, *pzb;
    __half *px16, *pxh, *pqn16, *py16, *pt16;
    __half *pwp, *pwvT, *pwo, *pwvo, *pw1, *pw2;
    cudaGetSymbolAddress((void**)&phh,   g_hhat);
    cudaGetSymbolAddress((void**)&pbvo,  g_bvo);
    cudaGetSymbolAddress((void**)&pzb,   g_zb);
    cudaGetSymbolAddress((void**)&px16,  g_x16);
    cudaGetSymbolAddress((void**)&pxh,   g_xh);
    cudaGetSymbolAddress((void**)&pqn16, g_qn16);
    cudaGetSymbolAddress((void**)&py16,  g_y16);
    cudaGetSymbolAddress((void**)&pt16,  g_t16);
    cudaGetSymbolAddress((void**)&pwp,   g_wp16);
    cudaGetSymbolAddress((void**)&pwvT,  g_wvT16);
    cudaGetSymbolAddress((void**)&pwo,   g_wo16);
    cudaGetSymbolAddress((void**)&pwvo,  g_wvo16);
    cudaGetSymbolAddress((void**)&pw1,   g_w1_16);
    cudaGetSymbolAddress((void**)&pw2,   g_w2_16);

    cudaFuncSetAttribute(gemmDualCvt, cudaFuncAttributeMaxDynamicSharedMemorySize, GSMEM);
    cudaFuncSetAttribute(gemmGateCvt, cudaFuncAttributeMaxDynamicSharedMemorySize, GSMEM);
    cudaFuncSetAttribute(gemmFFN,     cudaFuncAttributeMaxDynamicSharedMemorySize, GSMEM);

    // launch 0: prep (+ counter zero)
    prep<<<PREP_BLKS, 256>>>(
        W_proj, pwp, D_MODEL * 1024,
        out_w, pwo, D_MODEL * D_MODEL,
        x_t, px16, B_DIM * 1024,
        in_w + (size_t)2 * D_MODEL * D_MODEL, pwvT,
        out_w, in_b + 2 * D_MODEL, out_b, pbvo);

    const dim3 blk(256);

    // launch 1: gemmDualCvt = Wvo + G1 + w1 cvt
    gemmDualCvt<<<DUAL_BLKS, blk, GSMEM>>>(
        pwo, pwvT, pzb, pwvo,
        px16, pwp, b_proj, pxh,
        ffn_w1, pw1);
    // launch 2: L1
    ln2048_f16in<<<B_DIM, 256>>>(pxh, ln1_g, ln1_b, pqn16);
    // launch 3: gemmGateCvt = G23 + w2 cvt  <-- global ncu index 5
    gemmGateCvt<<<GATE_BLKS, blk, GSMEM>>>(
        pqn16, pwvo, pbvo, phh,
        h_prev, gate_a, gate_b,
        ffn_w2, pw2);
    // launch 4: L2
    ln2048_f32in<<<B_DIM, 256>>>(phh, ln2_g, ln2_b, py16);
    // launch 5: gemmFFN = G4 + G5 fused (counter-synced)
    float* out2 = (out_size >= 2 * B_DIM * D_MODEL) ? (out + (size_t)B_DIM * D_MODEL) : out;
    gemmFFN<<<FFN_BLKS, blk, GSMEM>>>(
        py16, pw1, ffn_b1, pt16,
        pw2, ffn_b2, phh,
        out, out2);
}